// round 9
// baseline (speedup 1.0000x reference)
#include <cuda_runtime.h>
#include <math.h>

#define DEPTH 24
#define DM    192
#define DI    384
#define DS    16
#define DR    12
#define BATCH 4
#define LSEQ  401
#define NCLS  22
#define XD    44
#define EPSV  1e-5f
#define NC    31
#define CL    13
#define ROWS  (BATCH*LSEQ)     // 1604
#define ROWS2 (2*BATCH*LSEQ)   // 3208
#define NBLK  296
#define NGEN  160

// ---------------- scratch ----------------------------------------------------
__device__ float g_res [ROWS*DM];
__device__ float g_hn  [ROWS*DM];
__device__ float g_xz  [ROWS*2*DI];
__device__ float g_xx  [ROWS2*DI];
__device__ float g_dt  [ROWS2*DI];
__device__ float g_dbl [ROWS2*XD];
__device__ float g_y   [ROWS2*DI];
__device__ float g_Aexp[2*DEPTH*DI*DS];
__device__ int   g_Aflag[2*DEPTH*DI];
__device__ float g_hloc[2*BATCH*NC*DS*DI];
__device__ float g_cin [2*BATCH*NC*DS*DI];
__device__ float g_S   [2*BATCH*NC*DI];
__device__ int   g_cnt [NGEN];
__device__ volatile int g_release;

__device__ __forceinline__ float siluf(float x) { return x / (1.f + __expf(-x)); }
__device__ __forceinline__ float softplusf(float x) {
    return x > 20.f ? x : log1pf(__expf(x));
}

// ------- single-hop barrier: atomic count per gen; last arriver releases -----
__device__ __forceinline__ void gbar(int gen) {
    __syncthreads();
    if (threadIdx.x == 0) {
        __threadfence();
        int old = atomicAdd(&g_cnt[gen], 1);
        if (old == NBLK - 1) {
            g_release = gen;
        } else {
            while (g_release < gen) __nanosleep(32);
        }
        __threadfence();
    }
    __syncthreads();
}

// ---------------- prep: A = -exp(A_log); detect geometric structure ----------
__global__ void k_prepA(const float* __restrict__ Alog, const float* __restrict__ Ablog) {
    int i = blockIdx.x * blockDim.x + threadIdx.x;
    if (i >= 2 * DEPTH * DI) return;
    int dir = i / (DEPTH * DI);
    int rest = i - dir * (DEPTH * DI);
    const float* src = (dir ? Ablog : Alog) + (size_t)rest * DS;
    float A[DS];
#pragma unroll
    for (int n = 0; n < DS; n++) A[n] = -__expf(src[n]);
    float A0 = A[0];
    bool ok = true;
#pragma unroll
    for (int n = 1; n < DS; n++) {
        float tgt = (float)(n + 1) * A0;
        ok = ok && (fabsf(A[n] - tgt) <= 1e-4f * fabsf(tgt) + 1e-30f);
    }
#pragma unroll
    for (int n = 0; n < DS; n++) g_Aexp[(size_t)i * DS + n] = A[n];
    g_Aflag[i] = ok ? 1 : 0;
}

// =============================================================================
// Whole network, one persistent kernel.
// =============================================================================
__global__ __launch_bounds__(256, 2)
void k_net(const float* __restrict__ x,   const float* __restrict__ pew,
           const float* __restrict__ peb, const float* __restrict__ cls,
           const float* __restrict__ pos, const float* __restrict__ norm_w,
           const float* __restrict__ ipw, const float* __restrict__ cw,
           const float* __restrict__ cb,  const float* __restrict__ xpw,
           const float* __restrict__ dtw, const float* __restrict__ dtb,
           const float* __restrict__ Dp,  const float* __restrict__ opw,
           const float* __restrict__ nfw, const float* __restrict__ hw,
           const float* __restrict__ hb,  float* __restrict__ out) {
    const int bid = blockIdx.x;
    const int tid = threadIdx.x;
    int gen = 0;
    __shared__ float sm[7424];
    __shared__ float red2[8];

    // ===== stage E: patch embed + cls + pos + layer-0 residual/norm ==========
    for (int p = bid; p < ROWS; p += NBLK) {
        int b = p / LSEQ, t = p % LSEQ;
        float v = 0.f;
        if (t == 0) {
            if (tid < DM) v = cls[tid] + pos[tid];
        } else {
            int pp = t - 1, ph = pp / 200, pw = pp % 200;
            sm[tid] = x[(size_t)b * 32 * 3200 + (size_t)(ph * 16 + tid / 16) * 3200
                        + pw * 16 + (tid % 16)];
            __syncthreads();
            if (tid < DM) {
                float acc = peb[tid];
                const float* wc = pew + (size_t)tid * 256;
#pragma unroll 8
                for (int i = 0; i < 256; i++) acc = fmaf(sm[i], __ldg(wc + i), acc);
                v = acc + pos[(size_t)t * DM + tid];
            }
        }
        float u = 2.f * v;
        float s = (tid < DM) ? u * u : 0.f;
#pragma unroll
        for (int ofs = 16; ofs > 0; ofs >>= 1) s += __shfl_xor_sync(0xffffffffu, s, ofs);
        if ((tid & 31) == 0 && tid < DM) red2[tid >> 5] = s;
        __syncthreads();
        if (tid < DM) {
            float tot = red2[0] + red2[1] + red2[2] + red2[3] + red2[4] + red2[5];
            float rs = rsqrtf(tot / (float)DM + EPSV);
            size_t o = (size_t)p * DM + tid;
            g_res[o] = u;
            g_hn[o]  = u * rs * norm_w[tid];
        }
        __syncthreads();
    }
    gbar(++gen);

    // ===== layer loop =========================================================
    for (int l = 0; l < DEPTH; l++) {
        const float* ipw_l = ipw + (size_t)l * 2 * DI * DM;
        const float* cw_l  = cw  + (size_t)l * DI * 4;
        const float* cb_l  = cb  + (size_t)l * DI;
        const float* xpw_l = xpw + (size_t)l * XD * DI;
        const float* dtw_l = dtw + (size_t)l * DI * DR;
        const float* dtb_l = dtb + (size_t)l * DI;
        const float* Dp_l  = Dp  + (size_t)l * DI;
        const float* opw_l = opw + (size_t)l * DM * DI;
        const float* nw_next = (l == DEPTH - 1) ? nfw : (norm_w + (size_t)(l + 1) * DM);

        // ---- S2: in_proj GEMM  xz[1604,768] = hn @ ipw^T  (80x64 tiles) -----
        {
            float* As = sm;                  // [16][84]
            float* Ws = sm + 16 * 84;        // [16][68]
            for (int tile = bid; tile < 21 * 12; tile += NBLK) {
                int bx = tile % 12, by = tile / 12;
                int row0 = by * 80, col0 = bx * 64;
                float acc[5][4];
#pragma unroll
                for (int i = 0; i < 5; i++)
#pragma unroll
                    for (int j = 0; j < 4; j++) acc[i][j] = 0.f;
                int ty = tid / 16, tx = tid % 16;
                for (int k0 = 0; k0 < DM; k0 += 16) {
                    for (int i = tid; i < 320; i += 256) {
                        int m = i >> 2, kq = i & 3;
                        float4 va = make_float4(0.f, 0.f, 0.f, 0.f);
                        if (row0 + m < ROWS)
                            va = __ldg((const float4*)(g_hn + (size_t)(row0 + m) * DM + k0 + kq * 4));
                        As[(kq * 4 + 0) * 84 + m] = va.x; As[(kq * 4 + 1) * 84 + m] = va.y;
                        As[(kq * 4 + 2) * 84 + m] = va.z; As[(kq * 4 + 3) * 84 + m] = va.w;
                    }
                    {
                        int n = tid >> 2, kq = tid & 3;
                        float4 vw = __ldg((const float4*)(ipw_l + (size_t)(col0 + n) * DM + k0 + kq * 4));
                        Ws[(kq * 4 + 0) * 68 + n] = vw.x; Ws[(kq * 4 + 1) * 68 + n] = vw.y;
                        Ws[(kq * 4 + 2) * 68 + n] = vw.z; Ws[(kq * 4 + 3) * 68 + n] = vw.w;
                    }
                    __syncthreads();
#pragma unroll
                    for (int k = 0; k < 16; k++) {
                        float ra[5];
#pragma unroll
                        for (int i = 0; i < 5; i++) ra[i] = As[k * 84 + ty * 5 + i];
                        float4 rb = *(const float4*)&Ws[k * 68 + tx * 4];
#pragma unroll
                        for (int i = 0; i < 5; i++) {
                            acc[i][0] = fmaf(ra[i], rb.x, acc[i][0]);
                            acc[i][1] = fmaf(ra[i], rb.y, acc[i][1]);
                            acc[i][2] = fmaf(ra[i], rb.z, acc[i][2]);
                            acc[i][3] = fmaf(ra[i], rb.w, acc[i][3]);
                        }
                    }
                    __syncthreads();
                }
#pragma unroll
                for (int i = 0; i < 5; i++) {
                    int r = row0 + ty * 5 + i;
                    if (r >= ROWS) continue;
                    *(float4*)&g_xz[(size_t)r * 2 * DI + col0 + tx * 4] =
                        make_float4(acc[i][0], acc[i][1], acc[i][2], acc[i][3]);
                }
            }
        }
        gbar(++gen);

        // ---- S4: conv+silu (into smem + g_xx) then dbl GEMM -----------------
        {
            float* As = sm;                  // [384][17] transposed conv output
            float* Ws = sm + 384 * 17;       // [16][52]
            for (int tile = bid; tile < 201; tile += NBLK) {
                int row0 = tile * 16;
                for (int idx = tid; idx < 16 * DI; idx += 256) {
                    int mm = idx / DI, d = idx - (idx / DI) * DI;
                    int r = row0 + mm;
                    if (r < ROWS2) {
                        int dir = r / ROWS;
                        int rem = r - dir * ROWS;
                        int b = rem / LSEQ, t = rem % LSEQ;
                        float4 w4 = __ldg((const float4*)(cw_l + d * 4));
                        float s = cb_l[d];
                        const float* xzb = g_xz + (size_t)b * LSEQ * 2 * DI + d;
                        if (dir == 0) {
                            if (t >= 3) s = fmaf(w4.x, xzb[(size_t)(t - 3) * 2 * DI], s);
                            if (t >= 2) s = fmaf(w4.y, xzb[(size_t)(t - 2) * 2 * DI], s);
                            if (t >= 1) s = fmaf(w4.z, xzb[(size_t)(t - 1) * 2 * DI], s);
                            s = fmaf(w4.w, xzb[(size_t)t * 2 * DI], s);
                        } else {
                            int base = LSEQ - 1 - t;
                            s = fmaf(w4.w, xzb[(size_t)base * 2 * DI], s);
                            if (t >= 1) s = fmaf(w4.z, xzb[(size_t)(base + 1) * 2 * DI], s);
                            if (t >= 2) s = fmaf(w4.y, xzb[(size_t)(base + 2) * 2 * DI], s);
                            if (t >= 3) s = fmaf(w4.x, xzb[(size_t)(base + 3) * 2 * DI], s);
                        }
                        float xv = siluf(s);
                        As[d * 17 + mm] = xv;
                        g_xx[(size_t)r * DI + d] = xv;
                    } else {
                        As[d * 17 + mm] = 0.f;
                    }
                }
                __syncthreads();
                float acc[3] = {0.f, 0.f, 0.f};
                int ty = tid / 16, tx = tid % 16;
                for (int k0 = 0; k0 < DI; k0 += 16) {
                    if (tid < 176) {
                        int n = tid >> 2, kq = tid & 3;
                        float4 v = __ldg((const float4*)(xpw_l + (size_t)n * DI + k0 + kq * 4));
                        Ws[(kq * 4 + 0) * 52 + n] = v.x; Ws[(kq * 4 + 1) * 52 + n] = v.y;
                        Ws[(kq * 4 + 2) * 52 + n] = v.z; Ws[(kq * 4 + 3) * 52 + n] = v.w;
                    }
                    __syncthreads();
#pragma unroll
                    for (int k = 0; k < 16; k++) {
                        float ra = As[(k0 + k) * 17 + ty];
#pragma unroll
                        for (int j = 0; j < 3; j++)
                            acc[j] = fmaf(ra, Ws[k * 52 + tx * 3 + j], acc[j]);
                    }
                    __syncthreads();
                }
                int r = row0 + ty;
                if (r < ROWS2) {
#pragma unroll
                    for (int j = 0; j < 3; j++) {
                        int n = tx * 3 + j;
                        if (n < XD) g_dbl[(size_t)r * XD + n] = acc[j];
                    }
                }
                __syncthreads();
            }
        }
        gbar(++gen);

        // ---- S5: scanA (chunk-local; dt_proj fused; stores dt) --------------
        if (bid < 2 * BATCH * NC) {
            int dir = bid / (BATCH * NC);
            int rem = bid - dir * (BATCH * NC);
            int b = rem / NC, c = rem % NC;
            size_t r0 = ((size_t)dir * BATCH + b) * LSEQ;
            int t0 = c * CL, t1 = min(LSEQ, t0 + CL);

#pragma unroll
            for (int u = 0; u < 2; u++) {
                int d = tid + u * 256;
                if (d >= DI) break;
                const float* Ap = g_Aexp + (((size_t)dir * DEPTH + l) * DI + d) * DS;
                float A0 = Ap[0];
                int flag = g_Aflag[((size_t)dir * DEPTH + l) * DI + d];
                float wdt[DR];
#pragma unroll
                for (int j = 0; j < DR; j++) wdt[j] = __ldg(dtw_l + (size_t)d * DR + j);
                float db0 = dtb_l[d], Dd = Dp_l[d];
                float h[DS];
#pragma unroll
                for (int n = 0; n < DS; n++) h[n] = 0.f;
                float S = 0.f;

                for (int t = t0; t < t1; t++) {
                    size_t r = r0 + t;
                    const float4* dbq = (const float4*)(g_dbl + r * XD);
                    float4 q0 = __ldg(dbq + 0), q1 = __ldg(dbq + 1), q2 = __ldg(dbq + 2);
                    float4 qB0 = __ldg(dbq + 3), qB1 = __ldg(dbq + 4),
                           qB2 = __ldg(dbq + 5), qB3 = __ldg(dbq + 6);
                    float4 qC0 = __ldg(dbq + 7), qC1 = __ldg(dbq + 8),
                           qC2 = __ldg(dbq + 9), qC3 = __ldg(dbq + 10);
                    float d1 = db0, d2 = 0.f;
                    d1 = fmaf(q0.x, wdt[0], d1); d2 = fmaf(q0.y, wdt[1], d2);
                    d1 = fmaf(q0.z, wdt[2], d1); d2 = fmaf(q0.w, wdt[3], d2);
                    d1 = fmaf(q1.x, wdt[4], d1); d2 = fmaf(q1.y, wdt[5], d2);
                    d1 = fmaf(q1.z, wdt[6], d1); d2 = fmaf(q1.w, wdt[7], d2);
                    d1 = fmaf(q2.x, wdt[8], d1); d2 = fmaf(q2.y, wdt[9], d2);
                    d1 = fmaf(q2.z, wdt[10], d1); d2 = fmaf(q2.w, wdt[11], d2);
                    float dt = softplusf(d1 + d2);
                    g_dt[r * DI + d] = dt;
                    float xv = g_xx[r * DI + d];
                    float dtx = dt * xv;
                    S += dt;
                    float Bv[DS] = {qB0.x, qB0.y, qB0.z, qB0.w, qB1.x, qB1.y, qB1.z, qB1.w,
                                    qB2.x, qB2.y, qB2.z, qB2.w, qB3.x, qB3.y, qB3.z, qB3.w};
                    float Cv[DS] = {qC0.x, qC0.y, qC0.z, qC0.w, qC1.x, qC1.y, qC1.z, qC1.w,
                                    qC2.x, qC2.y, qC2.z, qC2.w, qC3.x, qC3.y, qC3.z, qC3.w};
                    float acc = 0.f;
                    if (flag) {
                        float e = __expf(dt * A0);
                        float p = e;
#pragma unroll
                        for (int n = 0; n < DS; n++) {
                            h[n] = fmaf(p, h[n], dtx * Bv[n]);
                            acc = fmaf(h[n], Cv[n], acc);
                            p *= e;
                        }
                    } else {
#pragma unroll
                        for (int n = 0; n < DS; n++) {
                            float a = __expf(dt * __ldg(Ap + n));
                            h[n] = fmaf(a, h[n], dtx * Bv[n]);
                            acc = fmaf(h[n], Cv[n], acc);
                        }
                    }
                    g_y[r * DI + d] = acc + xv * Dd;
                }
                size_t cb_ = ((size_t)dir * BATCH + b) * NC + c;
#pragma unroll
                for (int n = 0; n < DS; n++) g_hloc[(cb_ * DS + n) * DI + d] = h[n];
                g_S[cb_ * DI + d] = S;
            }
        }
        gbar(++gen);

        // ---- S5b: O(NC) prefix combine — carry-in per chunk -----------------
        if (bid < 2 * BATCH) {
            int dir = bid / BATCH, b = bid % BATCH;
            size_t cb0 = ((size_t)dir * BATCH + b) * NC;
            for (int u = 0; u < 2; u++) {
                int d = tid + u * 256;
                if (d >= DI) break;
                const float* Ap = g_Aexp + (((size_t)dir * DEPTH + l) * DI + d) * DS;
                float A0 = Ap[0];
                int flag = g_Aflag[((size_t)dir * DEPTH + l) * DI + d];
                float g[DS];
#pragma unroll
                for (int n = 0; n < DS; n++) g[n] = 0.f;
                // prefetch chunk 0
                float Sc = g_S[cb0 * DI + d];
                float hl[DS];
#pragma unroll
                for (int n = 0; n < DS; n++) hl[n] = g_hloc[(cb0 * DS + n) * DI + d];
                for (int cc = 0; cc < NC - 1; cc++) {
                    float Sn = 0.f;
                    float hn2[DS];
                    if (cc + 1 < NC - 1) {
                        Sn = g_S[(cb0 + cc + 1) * DI + d];
#pragma unroll
                        for (int n = 0; n < DS; n++)
                            hn2[n] = g_hloc[((cb0 + cc + 1) * DS + n) * DI + d];
                    }
                    if (flag) {
                        float e = __expf(A0 * Sc);
                        float p = e;
#pragma unroll
                        for (int n = 0; n < DS; n++) {
                            g[n] = fmaf(p, g[n], hl[n]);
                            p *= e;
                        }
                    } else {
#pragma unroll
                        for (int n = 0; n < DS; n++)
                            g[n] = fmaf(__expf(__ldg(Ap + n) * Sc), g[n], hl[n]);
                    }
#pragma unroll
                    for (int n = 0; n < DS; n++)
                        g_cin[((cb0 + cc + 1) * DS + n) * DI + d] = g[n];
                    Sc = Sn;
#pragma unroll
                    for (int n = 0; n < DS; n++) hl[n] = hn2[n];
                }
            }
        }
        gbar(++gen);

        // ---- S6: scanC fixup (reads precomputed carry-in) -------------------
        if (bid < 2 * BATCH * (NC - 1)) {
            int dir = bid / (BATCH * (NC - 1));
            int rem = bid - dir * (BATCH * (NC - 1));
            int b = rem / (NC - 1), c = rem % (NC - 1) + 1;
            size_t r0 = ((size_t)dir * BATCH + b) * LSEQ;
            size_t cb0 = ((size_t)dir * BATCH + b) * NC;
            int t0 = c * CL, t1 = min(LSEQ, t0 + CL);

#pragma unroll
            for (int u = 0; u < 2; u++) {
                int d = tid + u * 256;
                if (d >= DI) break;
                const float* Ap = g_Aexp + (((size_t)dir * DEPTH + l) * DI + d) * DS;
                float A0 = Ap[0];
                int flag = g_Aflag[((size_t)dir * DEPTH + l) * DI + d];
                float g[DS];
#pragma unroll
                for (int n = 0; n < DS; n++)
                    g[n] = g_cin[((cb0 + c) * DS + n) * DI + d];

                for (int t = t0; t < t1; t++) {
                    size_t r = r0 + t;
                    const float4* dbq = (const float4*)(g_dbl + r * XD);
                    float4 qC0 = __ldg(dbq + 7), qC1 = __ldg(dbq + 8),
                           qC2 = __ldg(dbq + 9), qC3 = __ldg(dbq + 10);
                    float dt = g_dt[r * DI + d];
                    float Cv[DS] = {qC0.x, qC0.y, qC0.z, qC0.w, qC1.x, qC1.y, qC1.z, qC1.w,
                                    qC2.x, qC2.y, qC2.z, qC2.w, qC3.x, qC3.y, qC3.z, qC3.w};
                    float acc = 0.f;
                    if (flag) {
                        float e = __expf(dt * A0);
                        float p = e;
#pragma unroll
                        for (int n = 0; n < DS; n++) {
                            g[n] *= p;
                            acc = fmaf(g[n], Cv[n], acc);
                            p *= e;
                        }
                    } else {
#pragma unroll
                        for (int n = 0; n < DS; n++) {
                            g[n] *= __expf(dt * __ldg(Ap + n));
                            acc = fmaf(g[n], Cv[n], acc);
                        }
                    }
                    g_y[r * DI + d] += acc;
                }
            }
        }
        gbar(++gen);

        // ---- S7: out_proj GEMM (gated A) + residual + rmsnorm ---------------
        {
            float* As = sm;                  // [16][12]
            float* Ws = sm + 16 * 12;        // [16][196]
            for (int tile = bid; tile < 201; tile += NBLK) {
                int row0 = tile * 8;
                float acc[6] = {0.f, 0.f, 0.f, 0.f, 0.f, 0.f};
                for (int k0 = 0; k0 < DI; k0 += 16) {
                    if (tid < 32) {
                        int m = tid >> 2, kq = tid & 3;
                        int r = row0 + m;
                        float4 a = make_float4(0.f, 0.f, 0.f, 0.f);
                        if (r < ROWS) {
                            int b = r / LSEQ, t = r % LSEQ;
                            int d0 = k0 + kq * 4;
                            float4 yf = __ldg((const float4*)(g_y + (size_t)r * DI + d0));
                            size_t rb = ((size_t)(BATCH + b) * LSEQ + (LSEQ - 1 - t));
                            float4 yb = __ldg((const float4*)(g_y + rb * DI + d0));
                            float4 z4 = __ldg((const float4*)(g_xz + (size_t)r * 2 * DI + DI + d0));
                            a.x = (yf.x + yb.x) * siluf(z4.x);
                            a.y = (yf.y + yb.y) * siluf(z4.y);
                            a.z = (yf.z + yb.z) * siluf(z4.z);
                            a.w = (yf.w + yb.w) * siluf(z4.w);
                        }
                        As[(kq * 4 + 0) * 12 + m] = a.x; As[(kq * 4 + 1) * 12 + m] = a.y;
                        As[(kq * 4 + 2) * 12 + m] = a.z; As[(kq * 4 + 3) * 12 + m] = a.w;
                    }
                    for (int i = tid; i < 768; i += 256) {
                        int n = i >> 2, kq = i & 3;
                        float4 v = __ldg((const float4*)(opw_l + (size_t)n * DI + k0 + kq * 4));
                        Ws[(kq * 4 + 0) * 196 + n] = v.x; Ws[(kq * 4 + 1) * 196 + n] = v.y;
                        Ws[(kq * 4 + 2) * 196 + n] = v.z; Ws[(kq * 4 + 3) * 196 + n] = v.w;
                    }
                    __syncthreads();
                    int ty = tid >> 5, tx = tid & 31;
#pragma unroll
                    for (int k = 0; k < 16; k++) {
                        float ra = As[k * 12 + ty];
#pragma unroll
                        for (int j = 0; j < 6; j++)
                            acc[j] = fmaf(ra, Ws[k * 196 + tx * 6 + j], acc[j]);
                    }
                    __syncthreads();
                }
                int ty = tid >> 5, tx = tid & 31;
                int r = row0 + ty;
                bool valid = (r < ROWS);
                float v[6];
                float s = 0.f;
                if (valid) {
#pragma unroll
                    for (int j = 0; j < 6; j++) {
                        v[j] = g_res[(size_t)r * DM + tx * 6 + j] + acc[j];
                        s += v[j] * v[j];
                    }
                }
#pragma unroll
                for (int ofs = 16; ofs > 0; ofs >>= 1)
                    s += __shfl_xor_sync(0xffffffffu, s, ofs);
                float rs = rsqrtf(s / (float)DM + EPSV);
                if (valid) {
#pragma unroll
                    for (int j = 0; j < 6; j++) {
                        int cc = tx * 6 + j;
                        g_res[(size_t)r * DM + cc] = v[j];
                        g_hn[(size_t)r * DM + cc] = v[j] * rs * __ldg(nw_next + cc);
                    }
                }
                __syncthreads();
            }
        }
        if (l < DEPTH - 1) gbar(++gen);
    }

    // ===== final: arrive-only; block0 gathers, computes head, resets =========
    ++gen;
    __syncthreads();
    if (bid != 0) {
        if (tid == 0) {
            __threadfence();
            atomicAdd(&g_cnt[gen], 1);
        }
        return;
    }
    if (tid == 0) {
        while (atomicAdd(&g_cnt[gen], 0) < NBLK - 1) __nanosleep(64);
        __threadfence();
    }
    __syncthreads();
    if (tid < BATCH * NCLS) {
        int b = tid / NCLS, c = tid % NCLS;
        const float* row = g_hn + (size_t)b * LSEQ * DM;   // token 0, already normed
        float acc = hb[c];
        for (int j = 0; j < DM; j++) acc = fmaf(row[j], hw[(size_t)c * DM + j], acc);
        out[b * NCLS + c] = acc;
    }
    __syncthreads();
    for (int i = tid; i < NGEN; i += 256) g_cnt[i] = 0;
    __syncthreads();
    if (tid == 0) g_release = 0;
}

// ---------------- host --------------------------------------------------------
extern "C" void kernel_launch(void* const* d_in, const int* in_sizes, int n_in,
                              void* d_out, int out_size) {
    (void)in_sizes; (void)n_in; (void)out_size;
    const float* x      = (const float*)d_in[0];
    const float* pe_w   = (const float*)d_in[1];
    const float* pe_b   = (const float*)d_in[2];
    const float* cls    = (const float*)d_in[3];
    const float* pos    = (const float*)d_in[4];
    const float* norm_w = (const float*)d_in[5];
    const float* ipw    = (const float*)d_in[6];
    const float* cw     = (const float*)d_in[7];
    const float* cb     = (const float*)d_in[8];
    const float* xpw    = (const float*)d_in[9];
    const float* dtw    = (const float*)d_in[10];
    const float* dtb    = (const float*)d_in[11];
    const float* Alog   = (const float*)d_in[12];
    const float* Ablog  = (const float*)d_in[13];
    const float* Dp     = (const float*)d_in[14];
    const float* opw    = (const float*)d_in[15];
    const float* nfw    = (const float*)d_in[16];
    const float* hw     = (const float*)d_in[17];
    const float* hb     = (const float*)d_in[18];
    float* out = (float*)d_out;

    k_prepA<<<(2 * DEPTH * DI + 127) / 128, 128>>>(Alog, Ablog);
    k_net<<<NBLK, 256>>>(x, pe_w, pe_b, cls, pos, norm_w, ipw, cw, cb, xpw,
                         dtw, dtb, Dp, opw, nfw, hw, hb, out);
}

// round 10
// speedup vs baseline: 1.2566x; 1.2566x over previous
#include <cuda_runtime.h>
#include <math.h>

#define DEPTH 24
#define DM    192
#define DI    384
#define DS    16
#define DR    12
#define BATCH 4
#define LSEQ  401
#define NCLS  22
#define XD    44
#define EPSV  1e-5f
#define NC    31
#define CL    13
#define ROWS  (BATCH*LSEQ)     // 1604
#define ROWS2 (2*BATCH*LSEQ)   // 3208

// ---------------- scratch ----------------------------------------------------
__device__ float g_res [ROWS*DM];
__device__ float g_hn  [ROWS*DM];
__device__ float g_xz  [ROWS*2*DI];
__device__ float g_xx  [ROWS2*DI];
__device__ float g_dt  [ROWS2*DI];
__device__ float g_dbl [ROWS2*XD];
__device__ float g_y   [ROWS2*DI];
__device__ float g_Aexp[2*DEPTH*DI*DS];
__device__ int   g_Aflag[2*DEPTH*DI];
__device__ float g_hloc[2*BATCH*NC*DS*DI];
__device__ float g_S   [2*BATCH*NC*DI];

__device__ __forceinline__ float siluf(float x) { return x / (1.f + __expf(-x)); }
__device__ __forceinline__ float softplusf(float x) {
    return x > 20.f ? x : log1pf(__expf(x));
}

// ---------------- prep: A = -exp(A_log); detect geometric structure ----------
__global__ void k_prepA(const float* __restrict__ Alog, const float* __restrict__ Ablog) {
    int i = blockIdx.x * blockDim.x + threadIdx.x;
    if (i >= 2 * DEPTH * DI) return;
    int dir = i / (DEPTH * DI);
    int rest = i - dir * (DEPTH * DI);
    const float* src = (dir ? Ablog : Alog) + (size_t)rest * DS;
    float A[DS];
#pragma unroll
    for (int n = 0; n < DS; n++) A[n] = -__expf(src[n]);
    float A0 = A[0];
    bool ok = true;
#pragma unroll
    for (int n = 1; n < DS; n++) {
        float tgt = (float)(n + 1) * A0;
        ok = ok && (fabsf(A[n] - tgt) <= 1e-4f * fabsf(tgt) + 1e-30f);
    }
#pragma unroll
    for (int n = 0; n < DS; n++) g_Aexp[(size_t)i * DS + n] = A[n];
    g_Aflag[i] = ok ? 1 : 0;
}

// -------- patch embed + cls + pos + layer-0 residual(=2v) + rmsnorm ----------
__global__ void k_embed(const float* __restrict__ x, const float* __restrict__ pew,
                        const float* __restrict__ peb, const float* __restrict__ cls,
                        const float* __restrict__ pos, const float* __restrict__ nw0) {
    int t = blockIdx.x, b = blockIdx.y, c = threadIdx.x;
    float v;
    __shared__ float patch[256];
    __shared__ float red[6];
    if (t == 0) {
        v = cls[c] + pos[c];
    } else {
        int p = t - 1;
        int ph = p / 200, pw = p % 200;
        for (int i = c; i < 256; i += DM)
            patch[i] = x[(size_t)b * 32 * 3200 + (size_t)(ph * 16 + i / 16) * 3200
                         + pw * 16 + (i % 16)];
        __syncthreads();
        float acc = peb[c];
        const float* wc = pew + (size_t)c * 256;
#pragma unroll 8
        for (int i = 0; i < 256; i++) acc = fmaf(patch[i], __ldg(wc + i), acc);
        v = acc + pos[(size_t)t * DM + c];
    }
    float u = 2.f * v;                       // residual after layer-0 add
    size_t o = ((size_t)b * LSEQ + t) * DM + c;
    g_res[o] = u;
    float s = u * u;
#pragma unroll
    for (int ofs = 16; ofs > 0; ofs >>= 1) s += __shfl_xor_sync(0xffffffffu, s, ofs);
    if ((c & 31) == 0) red[c >> 5] = s;
    __syncthreads();
    float tot = red[0] + red[1] + red[2] + red[3] + red[4] + red[5];
    float rs = rsqrtf(tot / (float)DM + EPSV);
    g_hn[o] = u * rs * nw0[c];
}

// ---------------- generic SGEMM: C[M,N] = A[M,K] @ W[N,K]^T ------------------
template <int BM, int BN, int BK, int TM, int TN>
__global__ __launch_bounds__((BM / TM) * (BN / TN))
void sgemm_nt(const float* __restrict__ A, const float* __restrict__ W,
              float* __restrict__ C, int M, int N, int K) {
    constexpr int THR = (BM / TM) * (BN / TN);
    __shared__ float As[BK][BM + 4];
    __shared__ float Ws[BK][BN + 4];
    int tid = threadIdx.x;
    int tx = tid % (BN / TN);
    int ty = tid / (BN / TN);
    int row0 = blockIdx.y * BM;
    int col0 = blockIdx.x * BN;
    float acc[TM][TN];
#pragma unroll
    for (int i = 0; i < TM; i++)
#pragma unroll
        for (int j = 0; j < TN; j++) acc[i][j] = 0.f;

    for (int k0 = 0; k0 < K; k0 += BK) {
        for (int i = tid; i < BM * (BK / 4); i += THR) {
            int m = i / (BK / 4), kq = i % (BK / 4);
            float4 v = make_float4(0.f, 0.f, 0.f, 0.f);
            if (row0 + m < M)
                v = __ldg((const float4*)(A + (size_t)(row0 + m) * K + k0 + kq * 4));
            As[kq * 4 + 0][m] = v.x; As[kq * 4 + 1][m] = v.y;
            As[kq * 4 + 2][m] = v.z; As[kq * 4 + 3][m] = v.w;
        }
        for (int i = tid; i < BN * (BK / 4); i += THR) {
            int n = i / (BK / 4), kq = i % (BK / 4);
            float4 v = make_float4(0.f, 0.f, 0.f, 0.f);
            if (col0 + n < N)
                v = __ldg((const float4*)(W + (size_t)(col0 + n) * K + k0 + kq * 4));
            Ws[kq * 4 + 0][n] = v.x; Ws[kq * 4 + 1][n] = v.y;
            Ws[kq * 4 + 2][n] = v.z; Ws[kq * 4 + 3][n] = v.w;
        }
        __syncthreads();
#pragma unroll
        for (int k = 0; k < BK; k++) {
            float ra[TM], rb[TN];
#pragma unroll
            for (int i = 0; i < TM; i++) ra[i] = As[k][ty * TM + i];
#pragma unroll
            for (int j = 0; j < TN; j++) rb[j] = Ws[k][tx * TN + j];
#pragma unroll
            for (int i = 0; i < TM; i++)
#pragma unroll
                for (int j = 0; j < TN; j++) acc[i][j] = fmaf(ra[i], rb[j], acc[i][j]);
        }
        __syncthreads();
    }
#pragma unroll
    for (int i = 0; i < TM; i++) {
        int r = row0 + ty * TM + i;
        if (r >= M) continue;
#pragma unroll
        for (int j = 0; j < TN; j++) {
            int cc = col0 + tx * TN + j;
            if (cc < N) C[(size_t)r * N + cc] = acc[i][j];
        }
    }
}

// ------- fused: conv+silu (16 rows -> smem + g_xx) then dbl GEMM -------------
__global__ __launch_bounds__(256)
void k_convdbl(const float* __restrict__ cw_l, const float* __restrict__ cb_l,
               const float* __restrict__ xpw_l) {
    __shared__ float As[384 * 17];     // conv output, transposed [d][m]
    __shared__ float Ws[16 * 52];
    int tid = threadIdx.x;
    int row0 = blockIdx.x * 16;

    for (int idx = tid; idx < 16 * DI; idx += 256) {
        int mm = idx / DI, d = idx - (idx / DI) * DI;
        int r = row0 + mm;
        if (r < ROWS2) {
            int dir = r / ROWS;
            int rem = r - dir * ROWS;
            int b = rem / LSEQ, t = rem % LSEQ;
            float4 w4 = __ldg((const float4*)(cw_l + d * 4));
            float s = cb_l[d];
            const float* xzb = g_xz + (size_t)b * LSEQ * 2 * DI + d;
            if (dir == 0) {
                if (t >= 3) s = fmaf(w4.x, xzb[(size_t)(t - 3) * 2 * DI], s);
                if (t >= 2) s = fmaf(w4.y, xzb[(size_t)(t - 2) * 2 * DI], s);
                if (t >= 1) s = fmaf(w4.z, xzb[(size_t)(t - 1) * 2 * DI], s);
                s = fmaf(w4.w, xzb[(size_t)t * 2 * DI], s);
            } else {
                int base = LSEQ - 1 - t;
                s = fmaf(w4.w, xzb[(size_t)base * 2 * DI], s);
                if (t >= 1) s = fmaf(w4.z, xzb[(size_t)(base + 1) * 2 * DI], s);
                if (t >= 2) s = fmaf(w4.y, xzb[(size_t)(base + 2) * 2 * DI], s);
                if (t >= 3) s = fmaf(w4.x, xzb[(size_t)(base + 3) * 2 * DI], s);
            }
            float xv = siluf(s);
            As[d * 17 + mm] = xv;
            g_xx[(size_t)r * DI + d] = xv;
        } else {
            As[d * 17 + mm] = 0.f;
        }
    }
    __syncthreads();

    float acc[3] = {0.f, 0.f, 0.f};
    int ty = tid / 16, tx = tid % 16;
    for (int k0 = 0; k0 < DI; k0 += 16) {
        if (tid < 176) {
            int n = tid >> 2, kq = tid & 3;
            float4 v = __ldg((const float4*)(xpw_l + (size_t)n * DI + k0 + kq * 4));
            Ws[(kq * 4 + 0) * 52 + n] = v.x; Ws[(kq * 4 + 1) * 52 + n] = v.y;
            Ws[(kq * 4 + 2) * 52 + n] = v.z; Ws[(kq * 4 + 3) * 52 + n] = v.w;
        }
        __syncthreads();
#pragma unroll
        for (int k = 0; k < 16; k++) {
            float ra = As[(k0 + k) * 17 + ty];
#pragma unroll
            for (int j = 0; j < 3; j++)
                acc[j] = fmaf(ra, Ws[k * 52 + tx * 3 + j], acc[j]);
        }
        __syncthreads();
    }
    int r = row0 + ty;
    if (r < ROWS2) {
#pragma unroll
        for (int j = 0; j < 3; j++) {
            int n = tx * 3 + j;
            if (n < XD) g_dbl[(size_t)r * XD + n] = acc[j];
        }
    }
}

// ---------------- scan pass A: chunk-local scan (dt_proj fused, stores dt) ---
__global__ __launch_bounds__(DI)
void k_scanA(const float* __restrict__ dtw, const float* __restrict__ dtb,
             const float* __restrict__ Dpl, int l) {
    int dir = blockIdx.z, b = blockIdx.y, c = blockIdx.x;
    int d = threadIdx.x;
    const float* Ap = g_Aexp + (((size_t)dir * DEPTH + l) * DI + d) * DS;
    float A[DS];
#pragma unroll
    for (int n = 0; n < DS; n++) A[n] = Ap[n];
    int flag = g_Aflag[((size_t)dir * DEPTH + l) * DI + d];
    float A0 = A[0];
    float wdt[DR];
#pragma unroll
    for (int j = 0; j < DR; j++) wdt[j] = __ldg(dtw + (size_t)d * DR + j);
    float db0 = dtb[d], Dd = Dpl[d];

    size_t r0 = ((size_t)dir * BATCH + b) * LSEQ;
    int t0 = c * CL, t1 = min(LSEQ, t0 + CL);
    float h[DS];
#pragma unroll
    for (int n = 0; n < DS; n++) h[n] = 0.f;
    float S = 0.f;

    for (int t = t0; t < t1; t++) {
        size_t r = r0 + t;
        const float4* dbq = (const float4*)(g_dbl + r * XD);
        float4 q0 = __ldg(dbq + 0), q1 = __ldg(dbq + 1), q2 = __ldg(dbq + 2);
        float4 qB0 = __ldg(dbq + 3), qB1 = __ldg(dbq + 4),
               qB2 = __ldg(dbq + 5), qB3 = __ldg(dbq + 6);
        float4 qC0 = __ldg(dbq + 7), qC1 = __ldg(dbq + 8),
               qC2 = __ldg(dbq + 9), qC3 = __ldg(dbq + 10);
        float d1 = db0, d2 = 0.f;
        d1 = fmaf(q0.x, wdt[0], d1); d2 = fmaf(q0.y, wdt[1], d2);
        d1 = fmaf(q0.z, wdt[2], d1); d2 = fmaf(q0.w, wdt[3], d2);
        d1 = fmaf(q1.x, wdt[4], d1); d2 = fmaf(q1.y, wdt[5], d2);
        d1 = fmaf(q1.z, wdt[6], d1); d2 = fmaf(q1.w, wdt[7], d2);
        d1 = fmaf(q2.x, wdt[8], d1); d2 = fmaf(q2.y, wdt[9], d2);
        d1 = fmaf(q2.z, wdt[10], d1); d2 = fmaf(q2.w, wdt[11], d2);
        float dt = softplusf(d1 + d2);
        g_dt[r * DI + d] = dt;
        float xv = g_xx[r * DI + d];
        float dtx = dt * xv;
        S += dt;
        float Bv[DS] = {qB0.x, qB0.y, qB0.z, qB0.w, qB1.x, qB1.y, qB1.z, qB1.w,
                        qB2.x, qB2.y, qB2.z, qB2.w, qB3.x, qB3.y, qB3.z, qB3.w};
        float Cv[DS] = {qC0.x, qC0.y, qC0.z, qC0.w, qC1.x, qC1.y, qC1.z, qC1.w,
                        qC2.x, qC2.y, qC2.z, qC2.w, qC3.x, qC3.y, qC3.z, qC3.w};
        float acc = 0.f;
        if (flag) {
            float e = __expf(dt * A0);
            float p = e;
#pragma unroll
            for (int n = 0; n < DS; n++) {
                h[n] = fmaf(p, h[n], dtx * Bv[n]);
                acc = fmaf(h[n], Cv[n], acc);
                p *= e;
            }
        } else {
#pragma unroll
            for (int n = 0; n < DS; n++) {
                float a = __expf(dt * A[n]);
                h[n] = fmaf(a, h[n], dtx * Bv[n]);
                acc = fmaf(h[n], Cv[n], acc);
            }
        }
        g_y[r * DI + d] = acc + xv * Dd;
    }
    size_t cb_ = ((size_t)dir * BATCH + b) * NC + c;
#pragma unroll
    for (int n = 0; n < DS; n++) g_hloc[(cb_ * DS + n) * DI + d] = h[n];
    g_S[cb_ * DI + d] = S;
}

// ---------------- scan pass C: carry reconstruction + fixup (loads dt) -------
__global__ __launch_bounds__(DI)
void k_scanC(int l) {
    int dir = blockIdx.z, b = blockIdx.y, c = blockIdx.x + 1;
    int d = threadIdx.x;
    const float* Ap = g_Aexp + (((size_t)dir * DEPTH + l) * DI + d) * DS;
    float A[DS];
#pragma unroll
    for (int n = 0; n < DS; n++) A[n] = Ap[n];
    int flag = g_Aflag[((size_t)dir * DEPTH + l) * DI + d];
    float A0 = A[0];

    size_t cb0 = ((size_t)dir * BATCH + b) * NC;
    float g[DS];
#pragma unroll
    for (int n = 0; n < DS; n++) g[n] = 0.f;
    for (int cc = 0; cc < c; cc++) {
        float Sc = g_S[(cb0 + cc) * DI + d];
        if (flag) {
            float e = __expf(A0 * Sc);
            float p = e;
#pragma unroll
            for (int n = 0; n < DS; n++) {
                g[n] = fmaf(p, g[n], g_hloc[((cb0 + cc) * DS + n) * DI + d]);
                p *= e;
            }
        } else {
#pragma unroll
            for (int n = 0; n < DS; n++)
                g[n] = fmaf(__expf(A[n] * Sc), g[n],
                            g_hloc[((cb0 + cc) * DS + n) * DI + d]);
        }
    }

    size_t r0 = ((size_t)dir * BATCH + b) * LSEQ;
    int t0 = c * CL, t1 = min(LSEQ, t0 + CL);
    for (int t = t0; t < t1; t++) {
        size_t r = r0 + t;
        const float4* dbq = (const float4*)(g_dbl + r * XD);
        float4 qC0 = __ldg(dbq + 7), qC1 = __ldg(dbq + 8),
               qC2 = __ldg(dbq + 9), qC3 = __ldg(dbq + 10);
        float dt = g_dt[r * DI + d];
        float Cv[DS] = {qC0.x, qC0.y, qC0.z, qC0.w, qC1.x, qC1.y, qC1.z, qC1.w,
                        qC2.x, qC2.y, qC2.z, qC2.w, qC3.x, qC3.y, qC3.z, qC3.w};
        float acc = 0.f;
        if (flag) {
            float e = __expf(dt * A0);
            float p = e;
#pragma unroll
            for (int n = 0; n < DS; n++) {
                g[n] *= p;
                acc = fmaf(g[n], Cv[n], acc);
                p *= e;
            }
        } else {
#pragma unroll
            for (int n = 0; n < DS; n++) {
                g[n] *= __expf(dt * A[n]);
                acc = fmaf(g[n], Cv[n], acc);
            }
        }
        g_y[r * DI + d] += acc;
    }
}

// ------- out_proj GEMM (gated A) + residual add + rmsnorm epilogue -----------
// 8 rows x 192 cols per block; one warp owns one full output row.
__global__ __launch_bounds__(256)
void k_gemm_out(const float* __restrict__ opw_l, const float* __restrict__ nw_next) {
    __shared__ float As[16 * 12];
    __shared__ float Ws[16 * 196];
    int tid = threadIdx.x;
    int row0 = blockIdx.x * 8;
    float acc[6] = {0.f, 0.f, 0.f, 0.f, 0.f, 0.f};

    for (int k0 = 0; k0 < DI; k0 += 16) {
        if (tid < 32) {
            int m = tid >> 2, kq = tid & 3;
            int r = row0 + m;
            float4 a = make_float4(0.f, 0.f, 0.f, 0.f);
            if (r < ROWS) {
                int b = r / LSEQ, t = r % LSEQ;
                int d0 = k0 + kq * 4;
                float4 yf = __ldg((const float4*)(g_y + (size_t)r * DI + d0));
                size_t rb = ((size_t)(BATCH + b) * LSEQ + (LSEQ - 1 - t));
                float4 yb = __ldg((const float4*)(g_y + rb * DI + d0));
                float4 z4 = __ldg((const float4*)(g_xz + (size_t)r * 2 * DI + DI + d0));
                a.x = (yf.x + yb.x) * siluf(z4.x);
                a.y = (yf.y + yb.y) * siluf(z4.y);
                a.z = (yf.z + yb.z) * siluf(z4.z);
                a.w = (yf.w + yb.w) * siluf(z4.w);
            }
            As[(kq * 4 + 0) * 12 + m] = a.x; As[(kq * 4 + 1) * 12 + m] = a.y;
            As[(kq * 4 + 2) * 12 + m] = a.z; As[(kq * 4 + 3) * 12 + m] = a.w;
        }
        for (int i = tid; i < 768; i += 256) {
            int n = i >> 2, kq = i & 3;
            float4 v = __ldg((const float4*)(opw_l + (size_t)n * DI + k0 + kq * 4));
            Ws[(kq * 4 + 0) * 196 + n] = v.x; Ws[(kq * 4 + 1) * 196 + n] = v.y;
            Ws[(kq * 4 + 2) * 196 + n] = v.z; Ws[(kq * 4 + 3) * 196 + n] = v.w;
        }
        __syncthreads();
        int ty = tid >> 5, tx = tid & 31;
#pragma unroll
        for (int k = 0; k < 16; k++) {
            float ra = As[k * 12 + ty];
#pragma unroll
            for (int j = 0; j < 6; j++)
                acc[j] = fmaf(ra, Ws[k * 196 + tx * 6 + j], acc[j]);
        }
        __syncthreads();
    }
    // epilogue: v = res + acc; res = v; hn = rmsnorm(v) * nw_next
    int ty = tid >> 5, tx = tid & 31;
    int r = row0 + ty;
    bool valid = (r < ROWS);
    float v[6];
    float s = 0.f;
    if (valid) {
#pragma unroll
        for (int j = 0; j < 6; j++) {
            v[j] = g_res[(size_t)r * DM + tx * 6 + j] + acc[j];
            s += v[j] * v[j];
        }
    }
#pragma unroll
    for (int ofs = 16; ofs > 0; ofs >>= 1) s += __shfl_xor_sync(0xffffffffu, s, ofs);
    float rs = rsqrtf(s / (float)DM + EPSV);
    if (valid) {
#pragma unroll
        for (int j = 0; j < 6; j++) {
            int cc = tx * 6 + j;
            g_res[(size_t)r * DM + cc] = v[j];
            g_hn[(size_t)r * DM + cc] = v[j] * rs * __ldg(nw_next + cc);
        }
    }
}

// ---------------- final head: hn(token0, pre-normed) @ head^T + bias ---------
__global__ void k_final(const float* __restrict__ hw, const float* __restrict__ hb,
                        float* __restrict__ out) {
    int b = blockIdx.x;
    int c = threadIdx.x;
    if (c >= NCLS) return;
    const float* row = g_hn + (size_t)b * LSEQ * DM;
    float acc = hb[c];
    for (int j = 0; j < DM; j++) acc = fmaf(row[j], hw[(size_t)c * DM + j], acc);
    out[b * NCLS + c] = acc;
}

// ---------------- host --------------------------------------------------------
static float* symaddr(const void* sym) {
    void* p = nullptr;
    cudaGetSymbolAddress(&p, sym);
    return (float*)p;
}

extern "C" void kernel_launch(void* const* d_in, const int* in_sizes, int n_in,
                              void* d_out, int out_size) {
    (void)in_sizes; (void)n_in; (void)out_size;
    const float* x      = (const float*)d_in[0];
    const float* pe_w   = (const float*)d_in[1];
    const float* pe_b   = (const float*)d_in[2];
    const float* cls    = (const float*)d_in[3];
    const float* pos    = (const float*)d_in[4];
    const float* norm_w = (const float*)d_in[5];
    const float* ipw    = (const float*)d_in[6];
    const float* cw     = (const float*)d_in[7];
    const float* cb     = (const float*)d_in[8];
    const float* xpw    = (const float*)d_in[9];
    const float* dtw    = (const float*)d_in[10];
    const float* dtb    = (const float*)d_in[11];
    const float* Alog   = (const float*)d_in[12];
    const float* Ablog  = (const float*)d_in[13];
    const float* Dp     = (const float*)d_in[14];
    const float* opw    = (const float*)d_in[15];
    const float* nfw    = (const float*)d_in[16];
    const float* hw     = (const float*)d_in[17];
    const float* hb     = (const float*)d_in[18];
    float* out = (float*)d_out;

    float* p_hn  = symaddr(g_hn);
    float* p_xz  = symaddr(g_xz);

    k_prepA<<<(2 * DEPTH * DI + 127) / 128, 128>>>(Alog, Ablog);
    k_embed<<<dim3(LSEQ, BATCH), DM>>>(x, pe_w, pe_b, cls, pos, norm_w);

    for (int l = 0; l < DEPTH; l++) {
        // xz = hn @ ipw^T : M=1604, N=768, K=192  (312 blocks)
        sgemm_nt<64, 64, 16, 4, 4><<<dim3((2 * DI) / 64, (ROWS + 63) / 64), 256>>>(
            p_hn, ipw + (size_t)l * 2 * DI * DM, p_xz, ROWS, 2 * DI, DM);

        // conv+silu fused with dbl GEMM  (201 blocks)
        k_convdbl<<<(ROWS2 + 15) / 16, 256>>>(cw + (size_t)l * DI * 4,
                                              cb + (size_t)l * DI,
                                              xpw + (size_t)l * XD * DI);

        k_scanA<<<dim3(NC, BATCH, 2), DI>>>(dtw + (size_t)l * DI * DR,
                                            dtb + (size_t)l * DI,
                                            Dp + (size_t)l * DI, l);
        k_scanC<<<dim3(NC - 1, BATCH, 2), DI>>>(l);

        // out_proj + residual + rmsnorm (201 blocks)
        const float* nw_next = (l == DEPTH - 1) ? nfw : (norm_w + (size_t)(l + 1) * DM);
        k_gemm_out<<<(ROWS + 7) / 8, 256>>>(opw + (size_t)l * DM * DI, nw_next);
    }

    k_final<<<BATCH, 32>>>(hw, hb, out);
}

// round 11
// speedup vs baseline: 1.3102x; 1.0426x over previous
#include <cuda_runtime.h>
#include <math.h>

#define DEPTH 24
#define DM    192
#define DI    384
#define DS    16
#define DR    12
#define BATCH 4
#define LSEQ  401
#define NCLS  22
#define XD    44
#define EPSV  1e-5f
#define NC    31
#define CL    13
#define ROWS  (BATCH*LSEQ)     // 1604
#define ROWS2 (2*BATCH*LSEQ)   // 3208

// ---------------- scratch ----------------------------------------------------
__device__ float g_res [ROWS*DM];
__device__ float g_hid [ROWS*DM];
__device__ float g_hn  [ROWS*DM];
__device__ float g_xz  [ROWS*2*DI];
__device__ float g_xx  [ROWS2*DI];
__device__ float g_dbl [ROWS2*XD];
__device__ float g_y   [ROWS2*DI];
__device__ float g_Aexp[2*DEPTH*DI*DS];
__device__ int   g_Aflag[2*DEPTH*DI];
__device__ float g_hloc[2*BATCH*NC*DS*DI];
__device__ float g_S   [2*BATCH*NC*DI];

__device__ __forceinline__ float siluf(float x) { return x / (1.f + __expf(-x)); }
__device__ __forceinline__ float softplusf(float x) {
    return x > 20.f ? x : log1pf(__expf(x));
}

// ---------------- prep: A = -exp(A_log); detect geometric structure ----------
__global__ void k_prepA(const float* __restrict__ Alog, const float* __restrict__ Ablog) {
    int i = blockIdx.x * blockDim.x + threadIdx.x;
    if (i >= 2 * DEPTH * DI) return;
    int dir = i / (DEPTH * DI);
    int rest = i - dir * (DEPTH * DI);
    const float* src = (dir ? Ablog : Alog) + (size_t)rest * DS;
    float A[DS];
#pragma unroll
    for (int n = 0; n < DS; n++) A[n] = -__expf(src[n]);
    float A0 = A[0];
    bool ok = true;
#pragma unroll
    for (int n = 1; n < DS; n++) {
        float tgt = (float)(n + 1) * A0;
        ok = ok && (fabsf(A[n] - tgt) <= 1e-4f * fabsf(tgt) + 1e-30f);
    }
#pragma unroll
    for (int n = 0; n < DS; n++) g_Aexp[(size_t)i * DS + n] = A[n];
    g_Aflag[i] = ok ? 1 : 0;
}

// ---------------- patch embed + cls + pos ------------------------------------
__global__ void k_embed(const float* __restrict__ x, const float* __restrict__ pew,
                        const float* __restrict__ peb, const float* __restrict__ cls,
                        const float* __restrict__ pos) {
    int t = blockIdx.x, b = blockIdx.y, c = threadIdx.x;
    float v;
    __shared__ float patch[256];
    if (t == 0) {
        v = cls[c] + pos[c];
    } else {
        int p = t - 1;
        int ph = p / 200, pw = p % 200;
        for (int i = c; i < 256; i += DM)
            patch[i] = x[(size_t)b * 32 * 3200 + (size_t)(ph * 16 + i / 16) * 3200
                         + pw * 16 + (i % 16)];
        __syncthreads();
        float acc = peb[c];
        const float* wc = pew + (size_t)c * 256;
#pragma unroll 8
        for (int i = 0; i < 256; i++) acc = fmaf(patch[i], __ldg(wc + i), acc);
        v = acc + pos[(size_t)t * DM + c];
    }
    size_t o = ((size_t)b * LSEQ + t) * DM + c;
    g_res[o] = v;
    g_hid[o] = v;
}

// ---------------- residual += hidden; rmsnorm --------------------------------
__global__ void k_resnorm(const float* __restrict__ nw) {
    int r = blockIdx.x;
    int c = threadIdx.x;
    __shared__ float red[6];
    size_t o = (size_t)r * DM + c;
    float v = g_res[o] + g_hid[o];
    g_res[o] = v;
    float s = v * v;
#pragma unroll
    for (int ofs = 16; ofs > 0; ofs >>= 1) s += __shfl_xor_sync(0xffffffffu, s, ofs);
    if ((c & 31) == 0) red[c >> 5] = s;
    __syncthreads();
    float tot = red[0] + red[1] + red[2] + red[3] + red[4] + red[5];
    float rs = rsqrtf(tot / (float)DM + EPSV);
    g_hn[o] = v * rs * nw[c];
}

// ---------------- generic SGEMM: C[M,N] = A[M,K] @ W[N,K]^T ------------------
template <int BM, int BN, int BK, int TM, int TN>
__global__ __launch_bounds__((BM / TM) * (BN / TN))
void sgemm_nt(const float* __restrict__ A, const float* __restrict__ W,
              float* __restrict__ C, int M, int N, int K) {
    constexpr int THR = (BM / TM) * (BN / TN);
    __shared__ float As[BK][BM + 4];
    __shared__ float Ws[BK][BN + 4];
    int tid = threadIdx.x;
    int tx = tid % (BN / TN);
    int ty = tid / (BN / TN);
    int row0 = blockIdx.y * BM;
    int col0 = blockIdx.x * BN;
    float acc[TM][TN];
#pragma unroll
    for (int i = 0; i < TM; i++)
#pragma unroll
        for (int j = 0; j < TN; j++) acc[i][j] = 0.f;

    for (int k0 = 0; k0 < K; k0 += BK) {
        for (int i = tid; i < BM * (BK / 4); i += THR) {
            int m = i / (BK / 4), kq = i % (BK / 4);
            float4 v = make_float4(0.f, 0.f, 0.f, 0.f);
            if (row0 + m < M)
                v = __ldg((const float4*)(A + (size_t)(row0 + m) * K + k0 + kq * 4));
            As[kq * 4 + 0][m] = v.x; As[kq * 4 + 1][m] = v.y;
            As[kq * 4 + 2][m] = v.z; As[kq * 4 + 3][m] = v.w;
        }
        for (int i = tid; i < BN * (BK / 4); i += THR) {
            int n = i / (BK / 4), kq = i % (BK / 4);
            float4 v = make_float4(0.f, 0.f, 0.f, 0.f);
            if (col0 + n < N)
                v = __ldg((const float4*)(W + (size_t)(col0 + n) * K + k0 + kq * 4));
            Ws[kq * 4 + 0][n] = v.x; Ws[kq * 4 + 1][n] = v.y;
            Ws[kq * 4 + 2][n] = v.z; Ws[kq * 4 + 3][n] = v.w;
        }
        __syncthreads();
#pragma unroll
        for (int k = 0; k < BK; k++) {
            float ra[TM], rb[TN];
#pragma unroll
            for (int i = 0; i < TM; i++) ra[i] = As[k][ty * TM + i];
#pragma unroll
            for (int j = 0; j < TN; j++) rb[j] = Ws[k][tx * TN + j];
#pragma unroll
            for (int i = 0; i < TM; i++)
#pragma unroll
                for (int j = 0; j < TN; j++) acc[i][j] = fmaf(ra[i], rb[j], acc[i][j]);
        }
        __syncthreads();
    }
#pragma unroll
    for (int i = 0; i < TM; i++) {
        int r = row0 + ty * TM + i;
        if (r >= M) continue;
#pragma unroll
        for (int j = 0; j < TN; j++) {
            int cc = col0 + tx * TN + j;
            if (cc < N) C[(size_t)r * N + cc] = acc[i][j];
        }
    }
}

// ---------------- out_proj GEMM with gated A: A = (yf+yb)*silu(z) ------------
// 16x64 tiles, TM=1 TN=2, 512 threads, grid(3, 101) = 303 blocks.
#define OP_BM 16
#define OP_BN 64
#define OP_BK 16
__global__ __launch_bounds__(512)
void k_gemm_out(const float* __restrict__ W) {
    __shared__ float As[OP_BK][OP_BM + 4];
    __shared__ float Ws[OP_BK][OP_BN + 4];
    int tid = threadIdx.x;
    int tx = tid % 32;            // BN/TN = 64/2
    int ty = tid / 32;            // 0..15
    int row0 = blockIdx.y * OP_BM;
    int col0 = blockIdx.x * OP_BN;
    float acc[2] = {0.f, 0.f};

    for (int k0 = 0; k0 < DI; k0 += OP_BK) {
        if (tid < OP_BM * (OP_BK / 4)) {         // 64 loader tasks
            int m = tid >> 2, kq = tid & 3;
            int r = row0 + m;
            float4 a = make_float4(0.f, 0.f, 0.f, 0.f);
            if (r < ROWS) {
                int b = r / LSEQ, t = r % LSEQ;
                int d0 = k0 + kq * 4;
                float4 yf = __ldg((const float4*)(g_y + (size_t)r * DI + d0));
                size_t rb = ((size_t)(BATCH + b) * LSEQ + (LSEQ - 1 - t));
                float4 yb = __ldg((const float4*)(g_y + rb * DI + d0));
                float4 z4 = __ldg((const float4*)(g_xz + (size_t)r * 2 * DI + DI + d0));
                a.x = (yf.x + yb.x) * siluf(z4.x);
                a.y = (yf.y + yb.y) * siluf(z4.y);
                a.z = (yf.z + yb.z) * siluf(z4.z);
                a.w = (yf.w + yb.w) * siluf(z4.w);
            }
            As[kq * 4 + 0][m] = a.x; As[kq * 4 + 1][m] = a.y;
            As[kq * 4 + 2][m] = a.z; As[kq * 4 + 3][m] = a.w;
        } else if (tid >= 256 && tid < 256 + OP_BN * (OP_BK / 4)) {   // 256 W tasks
            int i = tid - 256;
            int n = i >> 2, kq = i & 3;
            float4 v = __ldg((const float4*)(W + (size_t)(col0 + n) * DI + k0 + kq * 4));
            Ws[kq * 4 + 0][n] = v.x; Ws[kq * 4 + 1][n] = v.y;
            Ws[kq * 4 + 2][n] = v.z; Ws[kq * 4 + 3][n] = v.w;
        }
        __syncthreads();
#pragma unroll
        for (int k = 0; k < OP_BK; k++) {
            float ra = As[k][ty];
            acc[0] = fmaf(ra, Ws[k][tx * 2 + 0], acc[0]);
            acc[1] = fmaf(ra, Ws[k][tx * 2 + 1], acc[1]);
        }
        __syncthreads();
    }
    int r = row0 + ty;
    if (r < ROWS) {
        g_hid[(size_t)r * DM + col0 + tx * 2 + 0] = acc[0];
        g_hid[(size_t)r * DM + col0 + tx * 2 + 1] = acc[1];
    }
}

// ---------------- causal depthwise conv + silu (both directions) -------------
#define CONV_TT 16
__global__ void k_conv(const float* __restrict__ cw, const float* __restrict__ cb) {
    int dir = blockIdx.z, b = blockIdx.y, tile = blockIdx.x;
    int d = threadIdx.x;
    float w0 = cw[d * 4 + 0], w1 = cw[d * 4 + 1], w2 = cw[d * 4 + 2], w3 = cw[d * 4 + 3];
    float bi = cb[d];
    const float* xzb = g_xz + (size_t)b * LSEQ * 2 * DI + d;
    int t0 = tile * CONV_TT, t1 = min(LSEQ, t0 + CONV_TT);
    for (int t = t0; t < t1; t++) {
        float s = bi;
        if (dir == 0) {
            if (t >= 3) s = fmaf(w0, xzb[(size_t)(t - 3) * 2 * DI], s);
            if (t >= 2) s = fmaf(w1, xzb[(size_t)(t - 2) * 2 * DI], s);
            if (t >= 1) s = fmaf(w2, xzb[(size_t)(t - 1) * 2 * DI], s);
            s = fmaf(w3, xzb[(size_t)t * 2 * DI], s);
        } else {
            int base = LSEQ - 1 - t;
            s = fmaf(w3, xzb[(size_t)base * 2 * DI], s);
            if (t >= 1) s = fmaf(w2, xzb[(size_t)(base + 1) * 2 * DI], s);
            if (t >= 2) s = fmaf(w1, xzb[(size_t)(base + 2) * 2 * DI], s);
            if (t >= 3) s = fmaf(w0, xzb[(size_t)(base + 3) * 2 * DI], s);
        }
        g_xx[(((size_t)dir * BATCH + b) * LSEQ + t) * DI + d] = siluf(s);
    }
}

// ---------------- scan pass A: chunk-local scan (dt_proj fused) --------------
__global__ __launch_bounds__(DI)
void k_scanA(const float* __restrict__ dtw, const float* __restrict__ dtb,
             const float* __restrict__ Dpl, int l) {
    int dir = blockIdx.z, b = blockIdx.y, c = blockIdx.x;
    int d = threadIdx.x;
    const float* Ap = g_Aexp + (((size_t)dir * DEPTH + l) * DI + d) * DS;
    float A[DS];
#pragma unroll
    for (int n = 0; n < DS; n++) A[n] = Ap[n];
    int flag = g_Aflag[((size_t)dir * DEPTH + l) * DI + d];
    float A0 = A[0];
    float wdt[DR];
#pragma unroll
    for (int j = 0; j < DR; j++) wdt[j] = __ldg(dtw + (size_t)d * DR + j);
    float db0 = dtb[d], Dd = Dpl[d];

    size_t r0 = ((size_t)dir * BATCH + b) * LSEQ;
    int t0 = c * CL, t1 = min(LSEQ, t0 + CL);
    float h[DS];
#pragma unroll
    for (int n = 0; n < DS; n++) h[n] = 0.f;
    float S = 0.f;

    for (int t = t0; t < t1; t++) {
        size_t r = r0 + t;
        const float4* dbq = (const float4*)(g_dbl + r * XD);
        float4 q0 = __ldg(dbq + 0), q1 = __ldg(dbq + 1), q2 = __ldg(dbq + 2);
        float4 qB0 = __ldg(dbq + 3), qB1 = __ldg(dbq + 4),
               qB2 = __ldg(dbq + 5), qB3 = __ldg(dbq + 6);
        float4 qC0 = __ldg(dbq + 7), qC1 = __ldg(dbq + 8),
               qC2 = __ldg(dbq + 9), qC3 = __ldg(dbq + 10);
        float d1 = db0, d2 = 0.f;
        d1 = fmaf(q0.x, wdt[0], d1); d2 = fmaf(q0.y, wdt[1], d2);
        d1 = fmaf(q0.z, wdt[2], d1); d2 = fmaf(q0.w, wdt[3], d2);
        d1 = fmaf(q1.x, wdt[4], d1); d2 = fmaf(q1.y, wdt[5], d2);
        d1 = fmaf(q1.z, wdt[6], d1); d2 = fmaf(q1.w, wdt[7], d2);
        d1 = fmaf(q2.x, wdt[8], d1); d2 = fmaf(q2.y, wdt[9], d2);
        d1 = fmaf(q2.z, wdt[10], d1); d2 = fmaf(q2.w, wdt[11], d2);
        float dt = softplusf(d1 + d2);
        float xv = g_xx[r * DI + d];
        float dtx = dt * xv;
        S += dt;
        float Bv[DS] = {qB0.x, qB0.y, qB0.z, qB0.w, qB1.x, qB1.y, qB1.z, qB1.w,
                        qB2.x, qB2.y, qB2.z, qB2.w, qB3.x, qB3.y, qB3.z, qB3.w};
        float Cv[DS] = {qC0.x, qC0.y, qC0.z, qC0.w, qC1.x, qC1.y, qC1.z, qC1.w,
                        qC2.x, qC2.y, qC2.z, qC2.w, qC3.x, qC3.y, qC3.z, qC3.w};
        float acc = 0.f;
        if (flag) {
            float e = __expf(dt * A0);
            float p = e;
#pragma unroll
            for (int n = 0; n < DS; n++) {
                h[n] = fmaf(p, h[n], dtx * Bv[n]);
                acc = fmaf(h[n], Cv[n], acc);
                p *= e;
            }
        } else {
#pragma unroll
            for (int n = 0; n < DS; n++) {
                float a = __expf(dt * A[n]);
                h[n] = fmaf(a, h[n], dtx * Bv[n]);
                acc = fmaf(h[n], Cv[n], acc);
            }
        }
        g_y[r * DI + d] = acc + xv * Dd;
    }
    size_t cb_ = ((size_t)dir * BATCH + b) * NC + c;
#pragma unroll
    for (int n = 0; n < DS; n++) g_hloc[(cb_ * DS + n) * DI + d] = h[n];
    g_S[cb_ * DI + d] = S;
}

// ---------------- scan pass C: carry-in reconstruction + fixup ---------------
__global__ __launch_bounds__(DI)
void k_scanC(const float* __restrict__ dtw, const float* __restrict__ dtb, int l) {
    int dir = blockIdx.z, b = blockIdx.y, c = blockIdx.x + 1;
    int d = threadIdx.x;
    const float* Ap = g_Aexp + (((size_t)dir * DEPTH + l) * DI + d) * DS;
    float A[DS];
#pragma unroll
    for (int n = 0; n < DS; n++) A[n] = Ap[n];
    int flag = g_Aflag[((size_t)dir * DEPTH + l) * DI + d];
    float A0 = A[0];
    float wdt[DR];
#pragma unroll
    for (int j = 0; j < DR; j++) wdt[j] = __ldg(dtw + (size_t)d * DR + j);
    float db0 = dtb[d];

    size_t cb0 = ((size_t)dir * BATCH + b) * NC;
    float g[DS];
#pragma unroll
    for (int n = 0; n < DS; n++) g[n] = 0.f;
    for (int cc = 0; cc < c; cc++) {
        float Sc = g_S[(cb0 + cc) * DI + d];
        if (flag) {
            float e = __expf(A0 * Sc);
            float p = e;
#pragma unroll
            for (int n = 0; n < DS; n++) {
                g[n] = fmaf(p, g[n], g_hloc[((cb0 + cc) * DS + n) * DI + d]);
                p *= e;
            }
        } else {
#pragma unroll
            for (int n = 0; n < DS; n++)
                g[n] = fmaf(__expf(A[n] * Sc), g[n],
                            g_hloc[((cb0 + cc) * DS + n) * DI + d]);
        }
    }

    size_t r0 = ((size_t)dir * BATCH + b) * LSEQ;
    int t0 = c * CL, t1 = min(LSEQ, t0 + CL);
    for (int t = t0; t < t1; t++) {
        size_t r = r0 + t;
        const float4* dbq = (const float4*)(g_dbl + r * XD);
        float4 q0 = __ldg(dbq + 0), q1 = __ldg(dbq + 1), q2 = __ldg(dbq + 2);
        float4 qC0 = __ldg(dbq + 7), qC1 = __ldg(dbq + 8),
               qC2 = __ldg(dbq + 9), qC3 = __ldg(dbq + 10);
        float d1 = db0, d2 = 0.f;
        d1 = fmaf(q0.x, wdt[0], d1); d2 = fmaf(q0.y, wdt[1], d2);
        d1 = fmaf(q0.z, wdt[2], d1); d2 = fmaf(q0.w, wdt[3], d2);
        d1 = fmaf(q1.x, wdt[4], d1); d2 = fmaf(q1.y, wdt[5], d2);
        d1 = fmaf(q1.z, wdt[6], d1); d2 = fmaf(q1.w, wdt[7], d2);
        d1 = fmaf(q2.x, wdt[8], d1); d2 = fmaf(q2.y, wdt[9], d2);
        d1 = fmaf(q2.z, wdt[10], d1); d2 = fmaf(q2.w, wdt[11], d2);
        float dt = softplusf(d1 + d2);
        float Cv[DS] = {qC0.x, qC0.y, qC0.z, qC0.w, qC1.x, qC1.y, qC1.z, qC1.w,
                        qC2.x, qC2.y, qC2.z, qC2.w, qC3.x, qC3.y, qC3.z, qC3.w};
        float acc = 0.f;
        if (flag) {
            float e = __expf(dt * A0);
            float p = e;
#pragma unroll
            for (int n = 0; n < DS; n++) {
                g[n] *= p;
                acc = fmaf(g[n], Cv[n], acc);
                p *= e;
            }
        } else {
#pragma unroll
            for (int n = 0; n < DS; n++) {
                g[n] *= __expf(dt * A[n]);
                acc = fmaf(g[n], Cv[n], acc);
            }
        }
        g_y[r * DI + d] += acc;
    }
}

// ---------------- final: norm token 0 + head ---------------------------------
__global__ void k_final(const float* __restrict__ nfw, const float* __restrict__ hw,
                        const float* __restrict__ hb, float* __restrict__ out) {
    int b = blockIdx.x;
    int c = threadIdx.x;
    __shared__ float vn[DM];
    __shared__ float red[6];
    size_t o = ((size_t)b * LSEQ) * DM + c;
    float v = g_res[o] + g_hid[o];
    float s = v * v;
#pragma unroll
    for (int ofs = 16; ofs > 0; ofs >>= 1) s += __shfl_xor_sync(0xffffffffu, s, ofs);
    if ((c & 31) == 0) red[c >> 5] = s;
    __syncthreads();
    float tot = red[0] + red[1] + red[2] + red[3] + red[4] + red[5];
    float rs = rsqrtf(tot / (float)DM + EPSV);
    vn[c] = v * rs * nfw[c];
    __syncthreads();
    if (c < NCLS) {
        float acc = hb[c];
        for (int j = 0; j < DM; j++) acc = fmaf(vn[j], hw[(size_t)c * DM + j], acc);
        out[b * NCLS + c] = acc;
    }
}

// ---------------- host --------------------------------------------------------
static float* symaddr(const void* sym) {
    void* p = nullptr;
    cudaGetSymbolAddress(&p, sym);
    return (float*)p;
}

extern "C" void kernel_launch(void* const* d_in, const int* in_sizes, int n_in,
                              void* d_out, int out_size) {
    (void)in_sizes; (void)n_in; (void)out_size;
    const float* x      = (const float*)d_in[0];
    const float* pe_w   = (const float*)d_in[1];
    const float* pe_b   = (const float*)d_in[2];
    const float* cls    = (const float*)d_in[3];
    const float* pos    = (const float*)d_in[4];
    const float* norm_w = (const float*)d_in[5];
    const float* ipw    = (const float*)d_in[6];
    const float* cw     = (const float*)d_in[7];
    const float* cb     = (const float*)d_in[8];
    const float* xpw    = (const float*)d_in[9];
    const float* dtw    = (const float*)d_in[10];
    const float* dtb    = (const float*)d_in[11];
    const float* Alog   = (const float*)d_in[12];
    const float* Ablog  = (const float*)d_in[13];
    const float* Dp     = (const float*)d_in[14];
    const float* opw    = (const float*)d_in[15];
    const float* nfw    = (const float*)d_in[16];
    const float* hw     = (const float*)d_in[17];
    const float* hb     = (const float*)d_in[18];
    float* out = (float*)d_out;

    float* p_hn  = symaddr(g_hn);
    float* p_xz  = symaddr(g_xz);
    float* p_xx  = symaddr(g_xx);
    float* p_dbl = symaddr(g_dbl);

    k_prepA<<<(2 * DEPTH * DI + 127) / 128, 128>>>(Alog, Ablog);
    k_embed<<<dim3(LSEQ, BATCH), DM>>>(x, pe_w, pe_b, cls, pos);

    for (int l = 0; l < DEPTH; l++) {
        k_resnorm<<<ROWS, DM>>>(norm_w + (size_t)l * DM);

        // xz = hn @ ipw^T : M=1604, N=768, K=192  (612 blocks, 33 warps/SM)
        sgemm_nt<32, 64, 16, 2, 4><<<dim3((2 * DI) / 64, (ROWS + 31) / 32), 256>>>(
            p_hn, ipw + (size_t)l * 2 * DI * DM, p_xz, ROWS, 2 * DI, DM);

        k_conv<<<dim3((LSEQ + CONV_TT - 1) / CONV_TT, BATCH, 2), DI>>>(
            cw + (size_t)l * DI * 4, cb + (size_t)l * DI);

        // dbl = xx @ xpw^T : M=3208, N=44, K=384  (201 blocks x 384 thr)
        sgemm_nt<16, 48, 16, 1, 2><<<dim3(1, (ROWS2 + 15) / 16), 384>>>(
            p_xx, xpw + (size_t)l * XD * DI, p_dbl, ROWS2, XD, DI);

        k_scanA<<<dim3(NC, BATCH, 2), DI>>>(dtw + (size_t)l * DI * DR,
                                            dtb + (size_t)l * DI,
                                            Dp + (size_t)l * DI, l);
        k_scanC<<<dim3(NC - 1, BATCH, 2), DI>>>(dtw + (size_t)l * DI * DR,
                                                dtb + (size_t)l * DI, l);

        // hid = gated @ opw^T (303 blocks x 512 thr, 33 warps/SM)
        k_gemm_out<<<dim3(DM / OP_BN, (ROWS + OP_BM - 1) / OP_BM), 512>>>(
            opw + (size_t)l * DM * DI);
    }

    k_final<<<BATCH, DM>>>(nfw, hw, hb, out);
}

// round 12
// speedup vs baseline: 1.3297x; 1.0149x over previous
#include <cuda_runtime.h>
#include <math.h>

#define DEPTH 24
#define DM    192
#define DI    384
#define DS    16
#define DR    12
#define BATCH 4
#define LSEQ  401
#define NCLS  22
#define XD    44
#define EPSV  1e-5f
#define NC    31
#define CL    13
#define ROWS  (BATCH*LSEQ)     // 1604
#define ROWS2 (2*BATCH*LSEQ)   // 3208

// ---------------- scratch ----------------------------------------------------
__device__ float g_res [ROWS*DM];
__device__ float g_hid [ROWS*DM];
__device__ float g_hid2[ROWS*DM];
__device__ float g_hn  [ROWS*DM];
__device__ float g_xz  [ROWS*2*DI];
__device__ float g_xx  [ROWS2*DI];
__device__ float g_dt  [ROWS2*DI];
__device__ float g_dbl [ROWS2*XD];
__device__ float g_dbl2[ROWS2*XD];
__device__ float g_y   [ROWS2*DI];
__device__ float g_Aexp[2*DEPTH*DI*DS];
__device__ int   g_Aflag[2*DEPTH*DI];
__device__ float g_hloc[2*BATCH*NC*DS*DI];
__device__ float g_S   [2*BATCH*NC*DI];

__device__ __forceinline__ float siluf(float x) { return x / (1.f + __expf(-x)); }
__device__ __forceinline__ float softplusf(float x) {
    return x > 20.f ? x : log1pf(__expf(x));
}
__device__ __forceinline__ float4 add4(float4 a, float4 b) {
    return make_float4(a.x + b.x, a.y + b.y, a.z + b.z, a.w + b.w);
}

// ---------------- prep: A = -exp(A_log); detect geometric structure ----------
__global__ void k_prepA(const float* __restrict__ Alog, const float* __restrict__ Ablog) {
    int i = blockIdx.x * blockDim.x + threadIdx.x;
    if (i >= 2 * DEPTH * DI) return;
    int dir = i / (DEPTH * DI);
    int rest = i - dir * (DEPTH * DI);
    const float* src = (dir ? Ablog : Alog) + (size_t)rest * DS;
    float A[DS];
#pragma unroll
    for (int n = 0; n < DS; n++) A[n] = -__expf(src[n]);
    float A0 = A[0];
    bool ok = true;
#pragma unroll
    for (int n = 1; n < DS; n++) {
        float tgt = (float)(n + 1) * A0;
        ok = ok && (fabsf(A[n] - tgt) <= 1e-4f * fabsf(tgt) + 1e-30f);
    }
#pragma unroll
    for (int n = 0; n < DS; n++) g_Aexp[(size_t)i * DS + n] = A[n];
    g_Aflag[i] = ok ? 1 : 0;
}

// ---------------- patch embed + cls + pos ------------------------------------
__global__ void k_embed(const float* __restrict__ x, const float* __restrict__ pew,
                        const float* __restrict__ peb, const float* __restrict__ cls,
                        const float* __restrict__ pos) {
    int t = blockIdx.x, b = blockIdx.y, c = threadIdx.x;
    float v;
    __shared__ float patch[256];
    if (t == 0) {
        v = cls[c] + pos[c];
    } else {
        int p = t - 1;
        int ph = p / 200, pw = p % 200;
        for (int i = c; i < 256; i += DM)
            patch[i] = x[(size_t)b * 32 * 3200 + (size_t)(ph * 16 + i / 16) * 3200
                         + pw * 16 + (i % 16)];
        __syncthreads();
        float acc = peb[c];
        const float* wc = pew + (size_t)c * 256;
#pragma unroll 8
        for (int i = 0; i < 256; i++) acc = fmaf(patch[i], __ldg(wc + i), acc);
        v = acc + pos[(size_t)t * DM + c];
    }
    size_t o = ((size_t)b * LSEQ + t) * DM + c;
    g_res[o] = v;
    g_hid[o] = v;
    g_hid2[o] = 0.f;
}

// ---------------- residual += hid + hid2; rmsnorm ----------------------------
__global__ void k_resnorm(const float* __restrict__ nw) {
    int r = blockIdx.x;
    int c = threadIdx.x;
    __shared__ float red[6];
    size_t o = (size_t)r * DM + c;
    float v = g_res[o] + g_hid[o] + g_hid2[o];
    g_res[o] = v;
    float s = v * v;
#pragma unroll
    for (int ofs = 16; ofs > 0; ofs >>= 1) s += __shfl_xor_sync(0xffffffffu, s, ofs);
    if ((c & 31) == 0) red[c >> 5] = s;
    __syncthreads();
    float tot = red[0] + red[1] + red[2] + red[3] + red[4] + red[5];
    float rs = rsqrtf(tot / (float)DM + EPSV);
    g_hn[o] = v * rs * nw[c];
}

// ---------------- generic SGEMM: C[M,N] = A[M,K] @ W[N,K]^T ------------------
template <int BM, int BN, int BK, int TM, int TN>
__global__ __launch_bounds__((BM / TM) * (BN / TN))
void sgemm_nt(const float* __restrict__ A, const float* __restrict__ W,
              float* __restrict__ C, int M, int N, int K) {
    constexpr int THR = (BM / TM) * (BN / TN);
    __shared__ float As[BK][BM + 4];
    __shared__ float Ws[BK][BN + 4];
    int tid = threadIdx.x;
    int tx = tid % (BN / TN);
    int ty = tid / (BN / TN);
    int row0 = blockIdx.y * BM;
    int col0 = blockIdx.x * BN;
    float acc[TM][TN];
#pragma unroll
    for (int i = 0; i < TM; i++)
#pragma unroll
        for (int j = 0; j < TN; j++) acc[i][j] = 0.f;

    for (int k0 = 0; k0 < K; k0 += BK) {
        for (int i = tid; i < BM * (BK / 4); i += THR) {
            int m = i / (BK / 4), kq = i % (BK / 4);
            float4 v = make_float4(0.f, 0.f, 0.f, 0.f);
            if (row0 + m < M)
                v = __ldg((const float4*)(A + (size_t)(row0 + m) * K + k0 + kq * 4));
            As[kq * 4 + 0][m] = v.x; As[kq * 4 + 1][m] = v.y;
            As[kq * 4 + 2][m] = v.z; As[kq * 4 + 3][m] = v.w;
        }
        for (int i = tid; i < BN * (BK / 4); i += THR) {
            int n = i / (BK / 4), kq = i % (BK / 4);
            float4 v = make_float4(0.f, 0.f, 0.f, 0.f);
            if (col0 + n < N)
                v = __ldg((const float4*)(W + (size_t)(col0 + n) * K + k0 + kq * 4));
            Ws[kq * 4 + 0][n] = v.x; Ws[kq * 4 + 1][n] = v.y;
            Ws[kq * 4 + 2][n] = v.z; Ws[kq * 4 + 3][n] = v.w;
        }
        __syncthreads();
#pragma unroll
        for (int k = 0; k < BK; k++) {
            float ra[TM], rb[TN];
#pragma unroll
            for (int i = 0; i < TM; i++) ra[i] = As[k][ty * TM + i];
#pragma unroll
            for (int j = 0; j < TN; j++) rb[j] = Ws[k][tx * TN + j];
#pragma unroll
            for (int i = 0; i < TM; i++)
#pragma unroll
                for (int j = 0; j < TN; j++) acc[i][j] = fmaf(ra[i], rb[j], acc[i][j]);
        }
        __syncthreads();
    }
#pragma unroll
    for (int i = 0; i < TM; i++) {
        int r = row0 + ty * TM + i;
        if (r >= M) continue;
#pragma unroll
        for (int j = 0; j < TN; j++) {
            int cc = col0 + tx * TN + j;
            if (cc < N) C[(size_t)r * N + cc] = acc[i][j];
        }
    }
}

// ---------------- dbl GEMM, K-split x2: z chooses K-half and output ----------
// C[3208, 44] partial = xx[:, kz*192:(kz+1)*192] @ xpw[:, same]^T
#define DB_BM 32
#define DB_BN 48
#define DB_BK 16
__global__ __launch_bounds__(256)
void k_gemm_dbl(const float* __restrict__ xx, const float* __restrict__ xpw_l) {
    __shared__ float As[DB_BK][DB_BM + 4];
    __shared__ float Ws[DB_BK][DB_BN + 4];
    int tid = threadIdx.x;
    int tx = tid % 16;           // BN/TN = 48/3
    int ty = tid / 16;           // BM/TM = 32/2
    int row0 = blockIdx.y * DB_BM;
    int kz = blockIdx.z;
    float* C = kz ? g_dbl2 : g_dbl;
    float acc[2][3] = {};

    int kbeg = kz * (DI / 2);
    for (int kk = 0; kk < DI / 2; kk += DB_BK) {
        int k0 = kbeg + kk;
        for (int i = tid; i < DB_BM * (DB_BK / 4); i += 256) {       // 128
            int m = i >> 2, kq = i & 3;
            float4 v = make_float4(0.f, 0.f, 0.f, 0.f);
            if (row0 + m < ROWS2)
                v = __ldg((const float4*)(xx + (size_t)(row0 + m) * DI + k0 + kq * 4));
            As[kq * 4 + 0][m] = v.x; As[kq * 4 + 1][m] = v.y;
            As[kq * 4 + 2][m] = v.z; As[kq * 4 + 3][m] = v.w;
        }
        for (int i = tid; i < DB_BN * (DB_BK / 4); i += 256) {       // 192
            int n = i >> 2, kq = i & 3;
            float4 v = make_float4(0.f, 0.f, 0.f, 0.f);
            if (n < XD)
                v = __ldg((const float4*)(xpw_l + (size_t)n * DI + k0 + kq * 4));
            Ws[kq * 4 + 0][n] = v.x; Ws[kq * 4 + 1][n] = v.y;
            Ws[kq * 4 + 2][n] = v.z; Ws[kq * 4 + 3][n] = v.w;
        }
        __syncthreads();
#pragma unroll
        for (int k = 0; k < DB_BK; k++) {
            float ra0 = As[k][ty * 2 + 0], ra1 = As[k][ty * 2 + 1];
            float rb0 = Ws[k][tx * 3 + 0], rb1 = Ws[k][tx * 3 + 1], rb2 = Ws[k][tx * 3 + 2];
            acc[0][0] = fmaf(ra0, rb0, acc[0][0]); acc[0][1] = fmaf(ra0, rb1, acc[0][1]);
            acc[0][2] = fmaf(ra0, rb2, acc[0][2]);
            acc[1][0] = fmaf(ra1, rb0, acc[1][0]); acc[1][1] = fmaf(ra1, rb1, acc[1][1]);
            acc[1][2] = fmaf(ra1, rb2, acc[1][2]);
        }
        __syncthreads();
    }
#pragma unroll
    for (int i = 0; i < 2; i++) {
        int r = row0 + ty * 2 + i;
        if (r >= ROWS2) continue;
#pragma unroll
        for (int j = 0; j < 3; j++) {
            int n = tx * 3 + j;
            if (n < XD) C[(size_t)r * XD + n] = acc[i][j];
        }
    }
}

// ------- out_proj GEMM, K-split x2, gated A: A = (yf+yb)*silu(z) -------------
#define OP_BM 32
#define OP_BN 64
#define OP_BK 16
__global__ __launch_bounds__(256)
void k_gemm_out(const float* __restrict__ W) {
    __shared__ float As[OP_BK][OP_BM + 4];
    __shared__ float Ws[OP_BK][OP_BN + 4];
    int tid = threadIdx.x;
    int tx = tid % 16;            // BN/TN = 64/4
    int ty = tid / 16;            // BM/TM = 32/2
    int row0 = blockIdx.y * OP_BM;
    int col0 = blockIdx.x * OP_BN;
    int kz = blockIdx.z;
    float* C = kz ? g_hid2 : g_hid;
    float acc[2][4] = {};

    int kbeg = kz * (DI / 2);
    for (int kk = 0; kk < DI / 2; kk += OP_BK) {
        int k0 = kbeg + kk;
        if (tid < OP_BM * (OP_BK / 4)) {         // 128 loader tasks
            int m = tid >> 2, kq = tid & 3;
            int r = row0 + m;
            float4 a = make_float4(0.f, 0.f, 0.f, 0.f);
            if (r < ROWS) {
                int b = r / LSEQ, t = r % LSEQ;
                int d0 = k0 + kq * 4;
                float4 yf = __ldg((const float4*)(g_y + (size_t)r * DI + d0));
                size_t rb = ((size_t)(BATCH + b) * LSEQ + (LSEQ - 1 - t));
                float4 yb = __ldg((const float4*)(g_y + rb * DI + d0));
                float4 z4 = __ldg((const float4*)(g_xz + (size_t)r * 2 * DI + DI + d0));
                a.x = (yf.x + yb.x) * siluf(z4.x);
                a.y = (yf.y + yb.y) * siluf(z4.y);
                a.z = (yf.z + yb.z) * siluf(z4.z);
                a.w = (yf.w + yb.w) * siluf(z4.w);
            }
            As[kq * 4 + 0][m] = a.x; As[kq * 4 + 1][m] = a.y;
            As[kq * 4 + 2][m] = a.z; As[kq * 4 + 3][m] = a.w;
        }
        for (int i = tid; i < OP_BN * (OP_BK / 4); i += 256) {   // 256 tasks
            int n = i >> 2, kq = i & 3;
            float4 v = __ldg((const float4*)(W + (size_t)(col0 + n) * DI + k0 + kq * 4));
            Ws[kq * 4 + 0][n] = v.x; Ws[kq * 4 + 1][n] = v.y;
            Ws[kq * 4 + 2][n] = v.z; Ws[kq * 4 + 3][n] = v.w;
        }
        __syncthreads();
#pragma unroll
        for (int k = 0; k < OP_BK; k++) {
            float ra0 = As[k][ty * 2 + 0], ra1 = As[k][ty * 2 + 1];
            float rb[4];
#pragma unroll
            for (int j = 0; j < 4; j++) rb[j] = Ws[k][tx * 4 + j];
#pragma unroll
            for (int j = 0; j < 4; j++) {
                acc[0][j] = fmaf(ra0, rb[j], acc[0][j]);
                acc[1][j] = fmaf(ra1, rb[j], acc[1][j]);
            }
        }
        __syncthreads();
    }
#pragma unroll
    for (int i = 0; i < 2; i++) {
        int r = row0 + ty * 2 + i;
        if (r >= ROWS) continue;
#pragma unroll
        for (int j = 0; j < 4; j++)
            C[(size_t)r * DM + col0 + tx * 4 + j] = acc[i][j];
    }
}

// ---------------- causal depthwise conv + silu (both directions) -------------
#define CONV_TT 16
__global__ void k_conv(const float* __restrict__ cw, const float* __restrict__ cb) {
    int dir = blockIdx.z, b = blockIdx.y, tile = blockIdx.x;
    int d = threadIdx.x;
    float w0 = cw[d * 4 + 0], w1 = cw[d * 4 + 1], w2 = cw[d * 4 + 2], w3 = cw[d * 4 + 3];
    float bi = cb[d];
    const float* xzb = g_xz + (size_t)b * LSEQ * 2 * DI + d;
    int t0 = tile * CONV_TT, t1 = min(LSEQ, t0 + CONV_TT);
    for (int t = t0; t < t1; t++) {
        float s = bi;
        if (dir == 0) {
            if (t >= 3) s = fmaf(w0, xzb[(size_t)(t - 3) * 2 * DI], s);
            if (t >= 2) s = fmaf(w1, xzb[(size_t)(t - 2) * 2 * DI], s);
            if (t >= 1) s = fmaf(w2, xzb[(size_t)(t - 1) * 2 * DI], s);
            s = fmaf(w3, xzb[(size_t)t * 2 * DI], s);
        } else {
            int base = LSEQ - 1 - t;
            s = fmaf(w3, xzb[(size_t)base * 2 * DI], s);
            if (t >= 1) s = fmaf(w2, xzb[(size_t)(base + 1) * 2 * DI], s);
            if (t >= 2) s = fmaf(w1, xzb[(size_t)(base + 2) * 2 * DI], s);
            if (t >= 3) s = fmaf(w0, xzb[(size_t)(base + 3) * 2 * DI], s);
        }
        g_xx[(((size_t)dir * BATCH + b) * LSEQ + t) * DI + d] = siluf(s);
    }
}

// ---------------- scan pass A: chunk-local scan (dt_proj fused, stores dt) ---
__global__ __launch_bounds__(DI)
void k_scanA(const float* __restrict__ dtw, const float* __restrict__ dtb,
             const float* __restrict__ Dpl, int l) {
    int dir = blockIdx.z, b = blockIdx.y, c = blockIdx.x;
    int d = threadIdx.x;
    const float* Ap = g_Aexp + (((size_t)dir * DEPTH + l) * DI + d) * DS;
    float A[DS];
#pragma unroll
    for (int n = 0; n < DS; n++) A[n] = Ap[n];
    int flag = g_Aflag[((size_t)dir * DEPTH + l) * DI + d];
    float A0 = A[0];
    float wdt[DR];
#pragma unroll
    for (int j = 0; j < DR; j++) wdt[j] = __ldg(dtw + (size_t)d * DR + j);
    float db0 = dtb[d], Dd = Dpl[d];

    size_t r0 = ((size_t)dir * BATCH + b) * LSEQ;
    int t0 = c * CL, t1 = min(LSEQ, t0 + CL);
    float h[DS];
#pragma unroll
    for (int n = 0; n < DS; n++) h[n] = 0.f;
    float S = 0.f;

    for (int t = t0; t < t1; t++) {
        size_t r = r0 + t;
        const float4* dbq  = (const float4*)(g_dbl  + r * XD);
        const float4* dbq2 = (const float4*)(g_dbl2 + r * XD);
        float4 q0 = add4(__ldg(dbq + 0), __ldg(dbq2 + 0));
        float4 q1 = add4(__ldg(dbq + 1), __ldg(dbq2 + 1));
        float4 q2 = add4(__ldg(dbq + 2), __ldg(dbq2 + 2));
        float4 qB0 = add4(__ldg(dbq + 3), __ldg(dbq2 + 3));
        float4 qB1 = add4(__ldg(dbq + 4), __ldg(dbq2 + 4));
        float4 qB2 = add4(__ldg(dbq + 5), __ldg(dbq2 + 5));
        float4 qB3 = add4(__ldg(dbq + 6), __ldg(dbq2 + 6));
        float4 qC0 = add4(__ldg(dbq + 7), __ldg(dbq2 + 7));
        float4 qC1 = add4(__ldg(dbq + 8), __ldg(dbq2 + 8));
        float4 qC2 = add4(__ldg(dbq + 9), __ldg(dbq2 + 9));
        float4 qC3 = add4(__ldg(dbq + 10), __ldg(dbq2 + 10));
        float d1 = db0, d2 = 0.f;
        d1 = fmaf(q0.x, wdt[0], d1); d2 = fmaf(q0.y, wdt[1], d2);
        d1 = fmaf(q0.z, wdt[2], d1); d2 = fmaf(q0.w, wdt[3], d2);
        d1 = fmaf(q1.x, wdt[4], d1); d2 = fmaf(q1.y, wdt[5], d2);
        d1 = fmaf(q1.z, wdt[6], d1); d2 = fmaf(q1.w, wdt[7], d2);
        d1 = fmaf(q2.x, wdt[8], d1); d2 = fmaf(q2.y, wdt[9], d2);
        d1 = fmaf(q2.z, wdt[10], d1); d2 = fmaf(q2.w, wdt[11], d2);
        float dt = softplusf(d1 + d2);
        g_dt[r * DI + d] = dt;
        float xv = g_xx[r * DI + d];
        float dtx = dt * xv;
        S += dt;
        float Bv[DS] = {qB0.x, qB0.y, qB0.z, qB0.w, qB1.x, qB1.y, qB1.z, qB1.w,
                        qB2.x, qB2.y, qB2.z, qB2.w, qB3.x, qB3.y, qB3.z, qB3.w};
        float Cv[DS] = {qC0.x, qC0.y, qC0.z, qC0.w, qC1.x, qC1.y, qC1.z, qC1.w,
                        qC2.x, qC2.y, qC2.z, qC2.w, qC3.x, qC3.y, qC3.z, qC3.w};
        float acc = 0.f;
        if (flag) {
            float e = __expf(dt * A0);
            float p = e;
#pragma unroll
            for (int n = 0; n < DS; n++) {
                h[n] = fmaf(p, h[n], dtx * Bv[n]);
                acc = fmaf(h[n], Cv[n], acc);
                p *= e;
            }
        } else {
#pragma unroll
            for (int n = 0; n < DS; n++) {
                float a = __expf(dt * A[n]);
                h[n] = fmaf(a, h[n], dtx * Bv[n]);
                acc = fmaf(h[n], Cv[n], acc);
            }
        }
        g_y[r * DI + d] = acc + xv * Dd;
    }
    size_t cb_ = ((size_t)dir * BATCH + b) * NC + c;
#pragma unroll
    for (int n = 0; n < DS; n++) g_hloc[(cb_ * DS + n) * DI + d] = h[n];
    g_S[cb_ * DI + d] = S;
}

// ---------------- scan pass C: carry reconstruction + fixup (loads dt) -------
__global__ __launch_bounds__(DI)
void k_scanC(int l) {
    int dir = blockIdx.z, b = blockIdx.y, c = blockIdx.x + 1;
    int d = threadIdx.x;
    const float* Ap = g_Aexp + (((size_t)dir * DEPTH + l) * DI + d) * DS;
    float A[DS];
#pragma unroll
    for (int n = 0; n < DS; n++) A[n] = Ap[n];
    int flag = g_Aflag[((size_t)dir * DEPTH + l) * DI + d];
    float A0 = A[0];

    size_t cb0 = ((size_t)dir * BATCH + b) * NC;
    float g[DS];
#pragma unroll
    for (int n = 0; n < DS; n++) g[n] = 0.f;
    for (int cc = 0; cc < c; cc++) {
        float Sc = g_S[(cb0 + cc) * DI + d];
        if (flag) {
            float e = __expf(A0 * Sc);
            float p = e;
#pragma unroll
            for (int n = 0; n < DS; n++) {
                g[n] = fmaf(p, g[n], g_hloc[((cb0 + cc) * DS + n) * DI + d]);
                p *= e;
            }
        } else {
#pragma unroll
            for (int n = 0; n < DS; n++)
                g[n] = fmaf(__expf(A[n] * Sc), g[n],
                            g_hloc[((cb0 + cc) * DS + n) * DI + d]);
        }
    }

    size_t r0 = ((size_t)dir * BATCH + b) * LSEQ;
    int t0 = c * CL, t1 = min(LSEQ, t0 + CL);
    for (int t = t0; t < t1; t++) {
        size_t r = r0 + t;
        const float4* dbq  = (const float4*)(g_dbl  + r * XD);
        const float4* dbq2 = (const float4*)(g_dbl2 + r * XD);
        float4 qC0 = add4(__ldg(dbq + 7), __ldg(dbq2 + 7));
        float4 qC1 = add4(__ldg(dbq + 8), __ldg(dbq2 + 8));
        float4 qC2 = add4(__ldg(dbq + 9), __ldg(dbq2 + 9));
        float4 qC3 = add4(__ldg(dbq + 10), __ldg(dbq2 + 10));
        float dt = g_dt[r * DI + d];
        float Cv[DS] = {qC0.x, qC0.y, qC0.z, qC0.w, qC1.x, qC1.y, qC1.z, qC1.w,
                        qC2.x, qC2.y, qC2.z, qC2.w, qC3.x, qC3.y, qC3.z, qC3.w};
        float acc = 0.f;
        if (flag) {
            float e = __expf(dt * A0);
            float p = e;
#pragma unroll
            for (int n = 0; n < DS; n++) {
                g[n] *= p;
                acc = fmaf(g[n], Cv[n], acc);
                p *= e;
            }
        } else {
#pragma unroll
            for (int n = 0; n < DS; n++) {
                g[n] *= __expf(dt * A[n]);
                acc = fmaf(g[n], Cv[n], acc);
            }
        }
        g_y[r * DI + d] += acc;
    }
}

// ---------------- final: norm token 0 + head ---------------------------------
__global__ void k_final(const float* __restrict__ nfw, const float* __restrict__ hw,
                        const float* __restrict__ hb, float* __restrict__ out) {
    int b = blockIdx.x;
    int c = threadIdx.x;
    __shared__ float vn[DM];
    __shared__ float red[6];
    size_t o = ((size_t)b * LSEQ) * DM + c;
    float v = g_res[o] + g_hid[o] + g_hid2[o];
    float s = v * v;
#pragma unroll
    for (int ofs = 16; ofs > 0; ofs >>= 1) s += __shfl_xor_sync(0xffffffffu, s, ofs);
    if ((c & 31) == 0) red[c >> 5] = s;
    __syncthreads();
    float tot = red[0] + red[1] + red[2] + red[3] + red[4] + red[5];
    float rs = rsqrtf(tot / (float)DM + EPSV);
    vn[c] = v * rs * nfw[c];
    __syncthreads();
    if (c < NCLS) {
        float acc = hb[c];
        for (int j = 0; j < DM; j++) acc = fmaf(vn[j], hw[(size_t)c * DM + j], acc);
        out[b * NCLS + c] = acc;
    }
}

// ---------------- host --------------------------------------------------------
static float* symaddr(const void* sym) {
    void* p = nullptr;
    cudaGetSymbolAddress(&p, sym);
    return (float*)p;
}

extern "C" void kernel_launch(void* const* d_in, const int* in_sizes, int n_in,
                              void* d_out, int out_size) {
    (void)in_sizes; (void)n_in; (void)out_size;
    const float* x      = (const float*)d_in[0];
    const float* pe_w   = (const float*)d_in[1];
    const float* pe_b   = (const float*)d_in[2];
    const float* cls    = (const float*)d_in[3];
    const float* pos    = (const float*)d_in[4];
    const float* norm_w = (const float*)d_in[5];
    const float* ipw    = (const float*)d_in[6];
    const float* cw     = (const float*)d_in[7];
    const float* cb     = (const float*)d_in[8];
    const float* xpw    = (const float*)d_in[9];
    const float* dtw    = (const float*)d_in[10];
    const float* dtb    = (const float*)d_in[11];
    const float* Alog   = (const float*)d_in[12];
    const float* Ablog  = (const float*)d_in[13];
    const float* Dp     = (const float*)d_in[14];
    const float* opw    = (const float*)d_in[15];
    const float* nfw    = (const float*)d_in[16];
    const float* hw     = (const float*)d_in[17];
    const float* hb     = (const float*)d_in[18];
    float* out = (float*)d_out;

    float* p_hn  = symaddr(g_hn);
    float* p_xz  = symaddr(g_xz);
    float* p_xx  = symaddr(g_xx);

    k_prepA<<<(2 * DEPTH * DI + 127) / 128, 128>>>(Alog, Ablog);
    k_embed<<<dim3(LSEQ, BATCH), DM>>>(x, pe_w, pe_b, cls, pos);

    for (int l = 0; l < DEPTH; l++) {
        k_resnorm<<<ROWS, DM>>>(norm_w + (size_t)l * DM);

        // xz = hn @ ipw^T : M=1604, N=768, K=192  (R3 measured-best: 312 blocks)
        sgemm_nt<64, 64, 16, 4, 4><<<dim3((2 * DI) / 64, (ROWS + 63) / 64), 256>>>(
            p_hn, ipw + (size_t)l * 2 * DI * DM, p_xz, ROWS, 2 * DI, DM);

        k_conv<<<dim3((LSEQ + CONV_TT - 1) / CONV_TT, BATCH, 2), DI>>>(
            cw + (size_t)l * DI * 4, cb + (size_t)l * DI);

        // dbl partials: K-split x2  (202 blocks)
        k_gemm_dbl<<<dim3(1, (ROWS2 + DB_BM - 1) / DB_BM, 2), 256>>>(
            p_xx, xpw + (size_t)l * XD * DI);

        k_scanA<<<dim3(NC, BATCH, 2), DI>>>(dtw + (size_t)l * DI * DR,
                                            dtb + (size_t)l * DI,
                                            Dp + (size_t)l * DI, l);
        k_scanC<<<dim3(NC - 1, BATCH, 2), DI>>>(l);

        // out_proj partials: K-split x2  (306 blocks)
        k_gemm_out<<<dim3(DM / OP_BN, (ROWS + OP_BM - 1) / OP_BM, 2), 256>>>(
            opw + (size_t)l * DM * DI);
    }

    k_final<<<BATCH, DM>>>(nfw, hw, hb, out);
}